// round 8
// baseline (speedup 1.0000x reference)
#include <cuda_runtime.h>
#include <cuda_bf16.h>
#include <cuda_fp8.h>
#include <math.h>
#include <stdint.h>

// ---------------- problem dims -------------------------------------------
#define Bc 4
#define Tc 4096
#define Dc 1024
#define Hc 1024
#define BHc (Bc * Hc)
#define NCHUNK 64
#define CLEN (Tc / NCHUNK)       // 64

// ---------------- GEMM geometry ------------------------------------------
// CTA tile 128(M) x 256(N). All K-tiles are 128 BYTES per row:
//   kt 0..15  : fp8 phase  (128 e4m3 / tile, K=2048) -> corrections
//   kt 16..31 : bf16 phase (64 bf16  / tile, K=1024) -> main product
#define BM 128
#define BN 256
#define NT_FP8 16
#define NTILES 32
#define STAGES 4
#define A_BYTES (BM * 128)       // 16384
#define B_BYTES (BN * 128)       // 32768
#define STAGE_BYTES (A_BYTES + B_BYTES)   // 49152
#define SMEM_TOTAL (STAGES * STAGE_BYTES) // 196608

// fp8 scales: (x_hi*32)*(W_lo*8192) and (x_lo*2048)*(W_hi*128) -> 2^18
#define INV_SCALE 3.814697265625e-06f     // 2^-18

// ---------------- scratch globals ----------------------------------------
__device__ __align__(1024) __nv_bfloat16 gx_hi[(size_t)Bc * Tc * Dc];  // 32MB
__device__ __align__(1024) __nv_bfloat16 gw_hi[2048 * 1024];           // [Wz;Wh]
__device__ __align__(1024) uint8_t gxc[(size_t)Bc * Tc * 2048];        // 32MB fp8
__device__ __align__(1024) uint8_t gwc[2048 * 2048];                   // 4MB fp8
__device__ float2 g_lcv[(size_t)Bc * Tc * Hc];                         // (lc, lv)
__device__ float g_A[NCHUNK * BHc];
__device__ float g_R[NCHUNK * BHc];
__device__ float g_hin[NCHUNK * BHc];

// ---------------- PTX helpers --------------------------------------------
__device__ __forceinline__ uint32_t smem_u32(const void* p) {
    uint32_t a;
    asm("{ .reg .u64 t; cvta.to.shared.u64 t, %1; cvt.u32.u64 %0, t; }"
        : "=r"(a) : "l"(p));
    return a;
}
__device__ __forceinline__ void cp_async16(uint32_t dst, const void* src) {
    asm volatile("cp.async.cg.shared.global [%0], [%1], 16;"
                 :: "r"(dst), "l"(src) : "memory");
}
#define CP_COMMIT() asm volatile("cp.async.commit_group;" ::: "memory")
#define CP_WAIT_2() asm volatile("cp.async.wait_group 2;" ::: "memory")

#define LDSM_X4(r0, r1, r2, r3, addr) \
    asm volatile("ldmatrix.sync.aligned.m8n8.x4.shared.b16 {%0,%1,%2,%3}, [%4];" \
                 : "=r"(r0), "=r"(r1), "=r"(r2), "=r"(r3) : "r"(addr))

__device__ __forceinline__ void mma_bf16(float* c, const uint32_t* a,
                                         const uint32_t* b) {
    asm volatile(
        "mma.sync.aligned.m16n8k16.row.col.f32.bf16.bf16.f32 "
        "{%0,%1,%2,%3}, {%4,%5,%6,%7}, {%8,%9}, {%0,%1,%2,%3};"
        : "+f"(c[0]), "+f"(c[1]), "+f"(c[2]), "+f"(c[3])
        : "r"(a[0]), "r"(a[1]), "r"(a[2]), "r"(a[3]), "r"(b[0]), "r"(b[1]));
}
__device__ __forceinline__ void mma_fp8(float* c, const uint32_t* a,
                                        const uint32_t* b) {
    asm volatile(
        "mma.sync.aligned.m16n8k32.row.col.f32.e4m3.e4m3.f32 "
        "{%0,%1,%2,%3}, {%4,%5,%6,%7}, {%8,%9}, {%0,%1,%2,%3};"
        : "+f"(c[0]), "+f"(c[1]), "+f"(c[2]), "+f"(c[3])
        : "r"(a[0]), "r"(a[1]), "r"(a[2]), "r"(a[3]), "r"(b[0]), "r"(b[1]));
}

// ---------------- math helpers -------------------------------------------
__device__ __forceinline__ float softplus_f(float u) {
    return fmaxf(u, 0.f) + __logf(1.f + __expf(-fabsf(u)));
}
__device__ __forceinline__ float log_g_f(float v) {
    return (v >= 0.f) ? __logf(v + 0.5f) : -softplus_f(-v);
}
__device__ __forceinline__ float logaddexp_f(float a, float b) {
    float m = fmaxf(a, b);
    if (m == -INFINITY) return -INFINITY;
    return m + __logf(1.f + __expf(-fabsf(a - b)));
}
// lc = -softplus(k), lsig = -softplus(-k); share log1p(e^-|k|).
__device__ __forceinline__ void lc_lsig(float k, float& lc, float& lsig) {
    float L = __logf(1.f + __expf(-fabsf(k)));
    lc   = -fmaxf(k, 0.f)  - L;
    lsig = -fmaxf(-k, 0.f) - L;
}
__device__ __forceinline__ uint32_t pack_fp8x4(float a, float b, float c, float d) {
    __nv_fp8x2_storage_t lo =
        __nv_cvt_float2_to_fp8x2(make_float2(a, b), __NV_SATFINITE, __NV_E4M3);
    __nv_fp8x2_storage_t hi =
        __nv_cvt_float2_to_fp8x2(make_float2(c, d), __NV_SATFINITE, __NV_E4M3);
    return (uint32_t)lo | ((uint32_t)hi << 16);
}

// ===========================================================================
// split kernel: x -> (gx_hi bf16, gxc fp8 pair), [Wz;Wh] -> (gw_hi, gwc)
// gxc row m (2048B): [0..1023] = fp8(x_hi*32), [1024..2047] = fp8(x_lo*2048)
// gwc row r (2048B): [0..1023] = fp8(W_lo*8192), [1024..2047] = fp8(W_hi*128)
// ===========================================================================
__global__ void split_kernel(const float4* __restrict__ x,
                             const float4* __restrict__ Wz,
                             const float4* __restrict__ Wh)
{
    int i = blockIdx.x * blockDim.x + threadIdx.x;   // < 4718592
    float4 v;
    uint2* dhi;
    uint8_t* cbase;
    float s_hi, s_lo;
    if (i < 4194304) {
        v = x[i];
        dhi = (uint2*)gx_hi + i;
        int m = i >> 8, d = (i & 255) << 2;
        cbase = gxc + (size_t)m * 2048 + d;
        s_hi = 32.f; s_lo = 2048.f;
    } else {
        int j = i - 4194304;                          // 0..524287
        v = (j < 262144) ? Wz[j] : Wh[j - 262144];
        dhi = (uint2*)gw_hi + j;
        int m = j >> 8, d = (j & 255) << 2;
        cbase = gwc + (size_t)m * 2048 + 1024 + d;    // hi part at +1024
        s_hi = 128.f; s_lo = 8192.f;
    }
    union { __nv_bfloat16 b[4]; uint2 u; } ph;
    ph.b[0] = __float2bfloat16_rn(v.x); ph.b[1] = __float2bfloat16_rn(v.y);
    ph.b[2] = __float2bfloat16_rn(v.z); ph.b[3] = __float2bfloat16_rn(v.w);
    float h0 = __bfloat162float(ph.b[0]), h1 = __bfloat162float(ph.b[1]);
    float h2 = __bfloat162float(ph.b[2]), h3 = __bfloat162float(ph.b[3]);
    *dhi = ph.u;
    uint32_t phi = pack_fp8x4(h0 * s_hi, h1 * s_hi, h2 * s_hi, h3 * s_hi);
    uint32_t plo = pack_fp8x4((v.x - h0) * s_lo, (v.y - h1) * s_lo,
                              (v.z - h2) * s_lo, (v.w - h3) * s_lo);
    if (i < 4194304) {        // x: hi at +0, lo at +1024
        *(uint32_t*)cbase = phi;
        *(uint32_t*)(cbase + 1024) = plo;
    } else {                  // W: lo at +0 (cbase already +1024 for hi)
        *(uint32_t*)(cbase - 1024) = plo;
        *(uint32_t*)cbase = phi;
    }
}

// ===========================================================================
// HMMA/QMMA GEMM + fused log-space epilogue
// ===========================================================================
__device__ __forceinline__ void load_tile(
    int kt, uint32_t sbase, int m0, int n0, int tid)
{
    const uint8_t *A, *B;
    int off;
    if (kt < NT_FP8) {
        A = gxc; B = gwc; off = kt << 7;
    } else {
        A = (const uint8_t*)gx_hi; B = (const uint8_t*)gw_hi;
        off = (kt - NT_FP8) << 7;
    }
    uint32_t bB = sbase + A_BYTES;
#pragma unroll
    for (int i = 0; i < 4; i++) {           // A: 128 rows x 8 chunks
        int idx = i * 256 + tid;
        int r = idx >> 3, c = idx & 7;
        uint32_t dst = sbase + r * 128 + ((c ^ (r & 7)) << 4);
        cp_async16(dst, A + (size_t)(m0 + r) * 2048 + off + (c << 4));
    }
#pragma unroll
    for (int i = 0; i < 8; i++) {           // B: 256 rows x 8 chunks
        int idx = i * 256 + tid;
        int r = idx >> 3, c = idx & 7;
        int j = r >> 6, w = r & 63;
        int grow = (w < 32) ? (n0 * 128 + j * 32 + w)
                            : (1024 + n0 * 128 + j * 32 + (w - 32));
        uint32_t dst = bB + r * 128 + ((c ^ (r & 7)) << 4);
        cp_async16(dst, B + (size_t)grow * 2048 + off + (c << 4));
    }
}

template <bool FP8>
__device__ __forceinline__ void compute_tile(
    uint32_t aB, uint32_t bB, float (*acc)[8][4],
    int warp_m, int warp_j, int a_row, int a_ch, int b_row, int b_kh, int b_td)
{
#pragma unroll
    for (int ks = 0; ks < 4; ks++) {
        uint32_t af[4][4];
#pragma unroll
        for (int mt = 0; mt < 4; mt++) {
            int r = warp_m * 64 + mt * 16 + a_row;
            int ch = (ks * 2 + a_ch) ^ (r & 7);
            LDSM_X4(af[mt][0], af[mt][1], af[mt][2], af[mt][3],
                    aB + r * 128 + ch * 16);
        }
        uint32_t bf[8][2];
#pragma unroll
        for (int tp = 0; tp < 4; tp++) {
            int tile = tp * 2 + b_td;
            int r = warp_j * 64 + tile * 8 + b_row;
            int ch = (ks * 2 + b_kh) ^ (r & 7);
            LDSM_X4(bf[tp * 2][0], bf[tp * 2][1],
                    bf[tp * 2 + 1][0], bf[tp * 2 + 1][1],
                    bB + r * 128 + ch * 16);
        }
#pragma unroll
        for (int mt = 0; mt < 4; mt++)
#pragma unroll
            for (int t = 0; t < 8; t++) {
                if (FP8) mma_fp8(acc[mt][t], af[mt], bf[t]);
                else     mma_bf16(acc[mt][t], af[mt], bf[t]);
            }
    }
}

__global__ void __launch_bounds__(256, 1) gemm_mma_kernel(
    const float* __restrict__ bz_g, const float* __restrict__ bh_g)
{
    extern __shared__ __align__(1024) char sm[];
    const uint32_t smem_base = smem_u32(sm);
    const int tid = threadIdx.x;
    const int lane = tid & 31;
    const int wid = tid >> 5;
    const int warp_m = wid >> 2;       // 0..1
    const int warp_j = wid & 3;        // 0..3
    const int n0 = blockIdx.x;         // 0..7
    const int m0 = blockIdx.y * BM;

    float acc[4][8][4];
#pragma unroll
    for (int a = 0; a < 4; a++)
#pragma unroll
        for (int b = 0; b < 8; b++)
#pragma unroll
            for (int c = 0; c < 4; c++) acc[a][b][c] = 0.f;

    load_tile(0, smem_base + 0 * STAGE_BYTES, m0, n0, tid); CP_COMMIT();
    load_tile(1, smem_base + 1 * STAGE_BYTES, m0, n0, tid); CP_COMMIT();
    load_tile(2, smem_base + 2 * STAGE_BYTES, m0, n0, tid); CP_COMMIT();

    const int a_row = lane & 15;
    const int a_ch  = lane >> 4;
    const int b_row = lane & 7;
    const int b_kh  = (lane >> 3) & 1;
    const int b_td  = lane >> 4;

    for (int kt = 0; kt < NTILES; ++kt) {
        CP_WAIT_2();
        __syncthreads();
        if (kt + 3 < NTILES)
            load_tile(kt + 3, smem_base + ((kt + 3) & 3) * STAGE_BYTES,
                      m0, n0, tid);
        CP_COMMIT();

        const uint32_t aB = smem_base + (kt & 3) * STAGE_BYTES;
        const uint32_t bB = aB + A_BYTES;
        if (kt < NT_FP8)
            compute_tile<true>(aB, bB, acc, warp_m, warp_j,
                               a_row, a_ch, b_row, b_kh, b_td);
        else
            compute_tile<false>(aB, bB, acc, warp_m, warp_j,
                                a_row, a_ch, b_row, b_kh, b_td);

        if (kt == NT_FP8 - 1) {        // rescale fp8 corrections once
#pragma unroll
            for (int a = 0; a < 4; a++)
#pragma unroll
                for (int b = 0; b < 8; b++)
#pragma unroll
                    for (int c = 0; c < 4; c++) acc[a][b][c] *= INV_SCALE;
        }
    }

    // ---------------- fused epilogue (in-register) ------------------------
    const int gr = lane >> 2;
    const int gc = (lane & 3) << 1;
#pragma unroll
    for (int t = 0; t < 4; t++) {
        int h = n0 * 128 + warp_j * 32 + t * 8 + gc;
        float bz0 = __ldg(bz_g + h),     bz1 = __ldg(bz_g + h + 1);
        float bh0 = __ldg(bh_g + h),     bh1 = __ldg(bh_g + h + 1);
#pragma unroll
        for (int mt = 0; mt < 4; mt++) {
            int r0 = m0 + warp_m * 64 + mt * 16 + gr;
            const float* ck = acc[mt][t];
            const float* ch = acc[mt][t + 4];
#pragma unroll
            for (int rr = 0; rr < 2; rr++) {
                float k0 = ck[rr * 2 + 0] + bz0;
                float k1 = ck[rr * 2 + 1] + bz1;
                float t0 = ch[rr * 2 + 0] + bh0;
                float t1 = ch[rr * 2 + 1] + bh1;
                float4 o;
                float ls0, ls1;
                lc_lsig(k0, o.x, ls0);
                lc_lsig(k1, o.z, ls1);
                o.y = ls0 + log_g_f(t0);
                o.w = ls1 + log_g_f(t1);
                *(float4*)((float*)g_lcv +
                           (((size_t)(r0 + rr * 8)) * Hc + h) * 2) = o;
            }
        }
    }
}

// ===========================================================================
// scans
// ===========================================================================
__global__ void scan_chunks_kernel()
{
    int g = blockIdx.x * blockDim.x + threadIdx.x;   // < NCHUNK * BHc / 2
    int p = g & (BHc / 2 - 1);
    int c = g >> 11;
    int b = p >> 9;
    int h = (p & 511) << 1;
    size_t base = ((size_t)b * Tc + (size_t)c * CLEN) * Hc + h;
    float A0 = 0.f, R0 = -INFINITY, A1 = 0.f, R1 = -INFINITY;
#pragma unroll 8
    for (int t = 0; t < CLEN; t++) {
        float4 v = *(const float4*)&g_lcv[base]; base += Hc;
        R0 = logaddexp_f(R0 + v.x, v.y); A0 += v.x;
        R1 = logaddexp_f(R1 + v.z, v.w); A1 += v.z;
    }
    int idx = c * BHc + b * Hc + h;
    g_A[idx] = A0; g_A[idx + 1] = A1;
    g_R[idx] = R0; g_R[idx + 1] = R1;
}

// warp-parallel combine: 1 warp per chain; lane handles chunks 2L, 2L+1;
// 5-step shuffle scan of affine ops (A, R) with
// compose(P then Q) = (P.A + Q.A, logaddexp(P.R + Q.A, Q.R)).
__global__ void scan_combine_kernel(const float* __restrict__ h0)
{
    int gt = blockIdx.x * blockDim.x + threadIdx.x;
    int w = gt >> 5;                   // chain id < 4096
    int lane = gt & 31;
    float lh0 = log_g_f(__ldg(h0 + w));
    int i0 = (lane * 2) * BHc + w;
    int i1 = i0 + BHc;
    float A0 = g_A[i0], R0 = g_R[i0];
    float A1 = g_A[i1], R1 = g_R[i1];
    float Ai = A0 + A1;
    float Ri = logaddexp_f(R0 + A1, R1);
#pragma unroll
    for (int d = 1; d < 32; d <<= 1) {
        float Au = __shfl_up_sync(0xFFFFFFFFu, Ai, d);
        float Ru = __shfl_up_sync(0xFFFFFFFFu, Ri, d);
        if (lane >= d) {
            Ri = logaddexp_f(Ru + Ai, Ri);
            Ai = Au + Ai;
        }
    }
    float Ae = __shfl_up_sync(0xFFFFFFFFu, Ai, 1);
    float Re = __shfl_up_sync(0xFFFFFFFFu, Ri, 1);
    if (lane == 0) { Ae = 0.f; Re = -INFINITY; }
    g_hin[i0] = logaddexp_f(Ae + lh0, Re);
    float Ae2 = Ae + A0;
    float Re2 = logaddexp_f(Re + A0, R0);
    g_hin[i1] = logaddexp_f(Ae2 + lh0, Re2);
}

__global__ void scan_final_kernel(float* __restrict__ out)
{
    int g = blockIdx.x * blockDim.x + threadIdx.x;   // < NCHUNK * BHc / 2
    int p = g & (BHc / 2 - 1);
    int c = g >> 11;
    int b = p >> 9;
    int h = (p & 511) << 1;
    size_t base = ((size_t)b * Tc + (size_t)c * CLEN) * Hc + h;
    int idx = c * BHc + b * Hc + h;
    float lh0 = g_hin[idx], lh1 = g_hin[idx + 1];
#pragma unroll 8
    for (int t = 0; t < CLEN; t++) {
        float4 v = *(const float4*)&g_lcv[base];
        lh0 = logaddexp_f(lh0 + v.x, v.y);
        lh1 = logaddexp_f(lh1 + v.z, v.w);
        float2 o; o.x = __expf(lh0); o.y = __expf(lh1);
        *(float2*)&out[base] = o;
        base += Hc;
    }
}

// ===========================================================================
extern "C" void kernel_launch(void* const* d_in, const int* in_sizes, int n_in,
                              void* d_out, int out_size)
{
    const float* x  = (const float*)d_in[0];
    const float* h0 = (const float*)d_in[1];
    const float* Wz = (const float*)d_in[2];
    const float* bz = (const float*)d_in[3];
    const float* Wh = (const float*)d_in[4];
    const float* bh = (const float*)d_in[5];
    float* out = (float*)d_out;

    cudaFuncSetAttribute(gemm_mma_kernel,
                         cudaFuncAttributeMaxDynamicSharedMemorySize, SMEM_TOTAL);

    split_kernel<<<18432, 256>>>((const float4*)x, (const float4*)Wz,
                                 (const float4*)Wh);

    dim3 ggrid(Hc / 128, (Bc * Tc) / BM);   // (8, 128)
    gemm_mma_kernel<<<ggrid, 256, SMEM_TOTAL>>>(bz, bh);

    scan_chunks_kernel<<<(NCHUNK * BHc / 2) / 256, 256>>>();
    scan_combine_kernel<<<(BHc * 32) / 256, 256>>>(h0);
    scan_final_kernel<<<(NCHUNK * BHc / 2) / 256, 256>>>(out);
}

// round 9
// speedup vs baseline: 1.1570x; 1.1570x over previous
#include <cuda_runtime.h>
#include <cuda_bf16.h>
#include <math.h>
#include <stdint.h>

// ---------------- problem dims -------------------------------------------
#define Bc 4
#define Tc 4096
#define Dc 1024
#define Hc 1024
#define BHc (Bc * Hc)
#define NCHUNK 64
#define CLEN (Tc / NCHUNK)       // 64

// ---------------- GEMM geometry ------------------------------------------
// CTA tile 256(M) x 128(N), 512 threads (16 warps), warp tile 64M x 32N.
// N rows interleave [Wz 16 | Wh 16] per 32-row j-block so each warp holds
// matching k / h~ columns. K tile 64 bf16; 48 tiles (hi*hi | lo*hi | hi*lo).
#define BM 256
#define BN 128
#define NTILES 48
#define STAGES 4
#define A_BYTES (BM * 128)       // 32768
#define B_BYTES (BN * 128)       // 16384
#define STAGE_BYTES (A_BYTES + B_BYTES)   // 49152
#define SMEM_TOTAL (STAGES * STAGE_BYTES) // 196608

// ---------------- scratch globals ----------------------------------------
__device__ __align__(1024) __nv_bfloat16 gx_hi[(size_t)Bc * Tc * Dc];
__device__ __align__(1024) __nv_bfloat16 gx_lo[(size_t)Bc * Tc * Dc];
__device__ __align__(1024) __nv_bfloat16 gw_hi[2048 * 1024];   // [Wz;Wh]
__device__ __align__(1024) __nv_bfloat16 gw_lo[2048 * 1024];
__device__ float2 g_lcv[(size_t)Bc * Tc * Hc];                 // (lc, lv)
__device__ float g_A[NCHUNK * BHc];
__device__ float g_R[NCHUNK * BHc];
__device__ float g_hin[NCHUNK * BHc];

// ---------------- PTX helpers --------------------------------------------
__device__ __forceinline__ uint32_t smem_u32(const void* p) {
    uint32_t a;
    asm("{ .reg .u64 t; cvta.to.shared.u64 t, %1; cvt.u32.u64 %0, t; }"
        : "=r"(a) : "l"(p));
    return a;
}
__device__ __forceinline__ void cp_async16(uint32_t dst, const void* src) {
    asm volatile("cp.async.cg.shared.global [%0], [%1], 16;"
                 :: "r"(dst), "l"(src) : "memory");
}
#define CP_COMMIT() asm volatile("cp.async.commit_group;" ::: "memory")
#define CP_WAIT_2() asm volatile("cp.async.wait_group 2;" ::: "memory")

#define LDSM_X4(r0, r1, r2, r3, addr) \
    asm volatile("ldmatrix.sync.aligned.m8n8.x4.shared.b16 {%0,%1,%2,%3}, [%4];" \
                 : "=r"(r0), "=r"(r1), "=r"(r2), "=r"(r3) : "r"(addr))

__device__ __forceinline__ void mma_bf16(float* c, const uint32_t* a,
                                         const uint32_t* b) {
    asm volatile(
        "mma.sync.aligned.m16n8k16.row.col.f32.bf16.bf16.f32 "
        "{%0,%1,%2,%3}, {%4,%5,%6,%7}, {%8,%9}, {%0,%1,%2,%3};"
        : "+f"(c[0]), "+f"(c[1]), "+f"(c[2]), "+f"(c[3])
        : "r"(a[0]), "r"(a[1]), "r"(a[2]), "r"(a[3]), "r"(b[0]), "r"(b[1]));
}

// ---------------- math helpers -------------------------------------------
__device__ __forceinline__ float softplus_f(float u) {
    return fmaxf(u, 0.f) + __logf(1.f + __expf(-fabsf(u)));
}
__device__ __forceinline__ float log_g_f(float v) {
    return (v >= 0.f) ? __logf(v + 0.5f) : -softplus_f(-v);
}
__device__ __forceinline__ float logaddexp_f(float a, float b) {
    float m = fmaxf(a, b);
    if (m == -INFINITY) return -INFINITY;
    return m + __logf(1.f + __expf(-fabsf(a - b)));
}
// lc = -softplus(k), lsig = -softplus(-k); share log1p(e^-|k|).
__device__ __forceinline__ void lc_lsig(float k, float& lc, float& lsig) {
    float L = __logf(1.f + __expf(-fabsf(k)));
    lc   = -fmaxf(k, 0.f)  - L;
    lsig = -fmaxf(-k, 0.f) - L;
}

// ===========================================================================
// merged bf16 split kernel: x (4,194,304 float4) then [Wz;Wh] (524,288 float4)
// ===========================================================================
__global__ void split_kernel(const float4* __restrict__ x,
                             const float4* __restrict__ Wz,
                             const float4* __restrict__ Wh)
{
    int i = blockIdx.x * blockDim.x + threadIdx.x;   // < 4718592
    float4 v;
    uint2 *dhi, *dlo;
    if (i < 4194304) {
        v = x[i];
        dhi = (uint2*)gx_hi + i;
        dlo = (uint2*)gx_lo + i;
    } else {
        int j = i - 4194304;                          // 0..524287
        v = (j < 262144) ? Wz[j] : Wh[j - 262144];
        dhi = (uint2*)gw_hi + j;
        dlo = (uint2*)gw_lo + j;
    }
    union { __nv_bfloat16 b[4]; uint2 u; } ph, pl;
    ph.b[0] = __float2bfloat16_rn(v.x); ph.b[1] = __float2bfloat16_rn(v.y);
    ph.b[2] = __float2bfloat16_rn(v.z); ph.b[3] = __float2bfloat16_rn(v.w);
    pl.b[0] = __float2bfloat16_rn(v.x - __bfloat162float(ph.b[0]));
    pl.b[1] = __float2bfloat16_rn(v.y - __bfloat162float(ph.b[1]));
    pl.b[2] = __float2bfloat16_rn(v.z - __bfloat162float(ph.b[2]));
    pl.b[3] = __float2bfloat16_rn(v.w - __bfloat162float(ph.b[3]));
    *dhi = ph.u;
    *dlo = pl.u;
}

// ===========================================================================
// HMMA GEMM + fused log-space epilogue. 512 threads, 16 warps,
// warp tile 64M x 32N (acc 64 regs). 4-stage cp.async pipeline.
// B-tile row r (0..127): j = r>>5 selects the warp-column's 16-wide h block,
// w = r&31: w<16 -> Wz row (n0*64 + j*16 + w), w>=16 -> Wh row (same h).
// ===========================================================================
__device__ __forceinline__ void load_tile(
    int kt, uint32_t sbase, int m0, int n0, int tid)
{
    int phase = kt >> 4;
    int kk = (kt & 15) << 6;
    const __nv_bfloat16* A = (phase == 1) ? gx_lo : gx_hi;
    const __nv_bfloat16* B = (phase == 2) ? gw_lo : gw_hi;
    uint32_t bB = sbase + A_BYTES;
#pragma unroll
    for (int i = 0; i < 4; i++) {           // A: 256 rows x 8 chunks
        int idx = i * 512 + tid;
        int r = idx >> 3, c = idx & 7;
        uint32_t dst = sbase + r * 128 + ((c ^ (r & 7)) << 4);
        cp_async16(dst, A + (((size_t)(m0 + r)) << 10) + kk + (c << 3));
    }
#pragma unroll
    for (int i = 0; i < 2; i++) {           // B: 128 rows x 8 chunks
        int idx = i * 512 + tid;
        int r = idx >> 3, c = idx & 7;
        int j = r >> 5, w = r & 31;
        int grow = (w < 16) ? (n0 * 64 + j * 16 + w)
                            : (1024 + n0 * 64 + j * 16 + (w - 16));
        uint32_t dst = bB + r * 128 + ((c ^ (r & 7)) << 4);
        cp_async16(dst, B + (((size_t)grow) << 10) + kk + (c << 3));
    }
}

__global__ void __launch_bounds__(512, 1) gemm_mma_kernel(
    const float* __restrict__ bz_g, const float* __restrict__ bh_g)
{
    extern __shared__ __align__(1024) char sm[];
    const uint32_t smem_base = smem_u32(sm);
    const int tid = threadIdx.x;
    const int lane = tid & 31;
    const int wid = tid >> 5;
    const int warp_m = wid >> 2;       // 0..3 : 64-row M quarter
    const int warp_j = wid & 3;        // 0..3 : 32-row N block (16 h)
    const int n0 = blockIdx.x;         // 0..15
    const int m0 = blockIdx.y * BM;

    float acc[4][4][4];
#pragma unroll
    for (int a = 0; a < 4; a++)
#pragma unroll
        for (int b = 0; b < 4; b++)
#pragma unroll
            for (int c = 0; c < 4; c++) acc[a][b][c] = 0.f;

    load_tile(0, smem_base + 0 * STAGE_BYTES, m0, n0, tid); CP_COMMIT();
    load_tile(1, smem_base + 1 * STAGE_BYTES, m0, n0, tid); CP_COMMIT();
    load_tile(2, smem_base + 2 * STAGE_BYTES, m0, n0, tid); CP_COMMIT();

    const int a_row = lane & 15;       // m within 16-tile
    const int a_ch  = lane >> 4;       // k half
    const int b_row = lane & 7;        // n within 8-tile
    const int b_kh  = (lane >> 3) & 1; // k half
    const int b_td  = lane >> 4;       // n8 tile within pair

    for (int kt = 0; kt < NTILES; ++kt) {
        CP_WAIT_2();                   // tile kt resident (this thread's part)
        __syncthreads();               // visible CTA-wide; prior compute done
        if (kt + 3 < NTILES)
            load_tile(kt + 3, smem_base + ((kt + 3) & 3) * STAGE_BYTES,
                      m0, n0, tid);
        CP_COMMIT();                   // empty group at tail keeps accounting

        const uint32_t aB = smem_base + (kt & 3) * STAGE_BYTES;
        const uint32_t bB = aB + A_BYTES;
#pragma unroll
        for (int ks = 0; ks < 4; ks++) {
            uint32_t af[4][4];
#pragma unroll
            for (int mt = 0; mt < 4; mt++) {
                int r = warp_m * 64 + mt * 16 + a_row;
                int ch = (ks * 2 + a_ch) ^ (r & 7);
                LDSM_X4(af[mt][0], af[mt][1], af[mt][2], af[mt][3],
                        aB + r * 128 + ch * 16);
            }
            uint32_t bf[4][2];
#pragma unroll
            for (int tp = 0; tp < 2; tp++) {
                int r = warp_j * 32 + tp * 16 + b_td * 8 + b_row;
                int ch = (ks * 2 + b_kh) ^ (r & 7);
                LDSM_X4(bf[tp * 2][0], bf[tp * 2][1],
                        bf[tp * 2 + 1][0], bf[tp * 2 + 1][1],
                        bB + r * 128 + ch * 16);
            }
#pragma unroll
            for (int mt = 0; mt < 4; mt++)
#pragma unroll
                for (int t = 0; t < 4; t++)
                    mma_bf16(acc[mt][t], af[mt], bf[t]);
        }
    }

    // ---------------- fused epilogue (in-register) ------------------------
    // t = 0..1 hold k, t = 2..3 hold h~ for the same h coordinates.
    const int gr = lane >> 2;            // 0..7  (row in m16 tile)
    const int gc = (lane & 3) << 1;      // 0,2,4,6 (col pair)
#pragma unroll
    for (int t = 0; t < 2; t++) {
        int h = n0 * 64 + warp_j * 16 + t * 8 + gc;
        float bz0 = __ldg(bz_g + h),     bz1 = __ldg(bz_g + h + 1);
        float bh0 = __ldg(bh_g + h),     bh1 = __ldg(bh_g + h + 1);
#pragma unroll
        for (int mt = 0; mt < 4; mt++) {
            int r0 = m0 + warp_m * 64 + mt * 16 + gr;
            const float* ck = acc[mt][t];
            const float* ch = acc[mt][t + 2];
#pragma unroll
            for (int rr = 0; rr < 2; rr++) {
                float k0 = ck[rr * 2 + 0] + bz0;
                float k1 = ck[rr * 2 + 1] + bz1;
                float t0 = ch[rr * 2 + 0] + bh0;
                float t1 = ch[rr * 2 + 1] + bh1;
                float4 o;
                float ls0, ls1;
                lc_lsig(k0, o.x, ls0);
                lc_lsig(k1, o.z, ls1);
                o.y = ls0 + log_g_f(t0);
                o.w = ls1 + log_g_f(t1);
                *(float4*)((float*)g_lcv +
                           (((size_t)(r0 + rr * 8)) * Hc + h) * 2) = o;
            }
        }
    }
}

// ===========================================================================
// chunked parallel scan (log-space):  lh <- logaddexp(lh + lc, lv)
// ===========================================================================
__global__ void scan_chunks_kernel()
{
    int g = blockIdx.x * blockDim.x + threadIdx.x;   // < NCHUNK * BHc / 2
    int p = g & (BHc / 2 - 1);
    int c = g >> 11;
    int b = p >> 9;
    int h = (p & 511) << 1;
    size_t base = ((size_t)b * Tc + (size_t)c * CLEN) * Hc + h;
    float A0 = 0.f, R0 = -INFINITY, A1 = 0.f, R1 = -INFINITY;
#pragma unroll 8
    for (int t = 0; t < CLEN; t++) {
        float4 v = *(const float4*)&g_lcv[base]; base += Hc;
        R0 = logaddexp_f(R0 + v.x, v.y); A0 += v.x;
        R1 = logaddexp_f(R1 + v.z, v.w); A1 += v.z;
    }
    int idx = c * BHc + b * Hc + h;
    g_A[idx] = A0; g_A[idx + 1] = A1;
    g_R[idx] = R0; g_R[idx + 1] = R1;
}

// warp-parallel combine: 1 warp per chain; lane handles chunks 2L, 2L+1;
// 5-step shuffle scan of affine ops (A, R) with
// compose(P then Q) = (P.A + Q.A, logaddexp(P.R + Q.A, Q.R)).
__global__ void scan_combine_kernel(const float* __restrict__ h0)
{
    int gt = blockIdx.x * blockDim.x + threadIdx.x;
    int w = gt >> 5;                   // chain id < 4096
    int lane = gt & 31;
    float lh0 = log_g_f(__ldg(h0 + w));
    int i0 = (lane * 2) * BHc + w;
    int i1 = i0 + BHc;
    float A0 = g_A[i0], R0 = g_R[i0];
    float A1 = g_A[i1], R1 = g_R[i1];
    float Ai = A0 + A1;
    float Ri = logaddexp_f(R0 + A1, R1);
#pragma unroll
    for (int d = 1; d < 32; d <<= 1) {
        float Au = __shfl_up_sync(0xFFFFFFFFu, Ai, d);
        float Ru = __shfl_up_sync(0xFFFFFFFFu, Ri, d);
        if (lane >= d) {
            Ri = logaddexp_f(Ru + Ai, Ri);
            Ai = Au + Ai;
        }
    }
    float Ae = __shfl_up_sync(0xFFFFFFFFu, Ai, 1);
    float Re = __shfl_up_sync(0xFFFFFFFFu, Ri, 1);
    if (lane == 0) { Ae = 0.f; Re = -INFINITY; }
    g_hin[i0] = logaddexp_f(Ae + lh0, Re);
    float Ae2 = Ae + A0;
    float Re2 = logaddexp_f(Re + A0, R0);
    g_hin[i1] = logaddexp_f(Ae2 + lh0, Re2);
}

__global__ void scan_final_kernel(float* __restrict__ out)
{
    int g = blockIdx.x * blockDim.x + threadIdx.x;   // < NCHUNK * BHc / 2
    int p = g & (BHc / 2 - 1);
    int c = g >> 11;
    int b = p >> 9;
    int h = (p & 511) << 1;
    size_t base = ((size_t)b * Tc + (size_t)c * CLEN) * Hc + h;
    int idx = c * BHc + b * Hc + h;
    float lh0 = g_hin[idx], lh1 = g_hin[idx + 1];
#pragma unroll 8
    for (int t = 0; t < CLEN; t++) {
        float4 v = *(const float4*)&g_lcv[base];
        lh0 = logaddexp_f(lh0 + v.x, v.y);
        lh1 = logaddexp_f(lh1 + v.z, v.w);
        float2 o; o.x = __expf(lh0); o.y = __expf(lh1);
        *(float2*)&out[base] = o;
        base += Hc;
    }
}

// ===========================================================================
extern "C" void kernel_launch(void* const* d_in, const int* in_sizes, int n_in,
                              void* d_out, int out_size)
{
    const float* x  = (const float*)d_in[0];
    const float* h0 = (const float*)d_in[1];
    const float* Wz = (const float*)d_in[2];
    const float* bz = (const float*)d_in[3];
    const float* Wh = (const float*)d_in[4];
    const float* bh = (const float*)d_in[5];
    float* out = (float*)d_out;

    cudaFuncSetAttribute(gemm_mma_kernel,
                         cudaFuncAttributeMaxDynamicSharedMemorySize, SMEM_TOTAL);

    split_kernel<<<18432, 256>>>((const float4*)x, (const float4*)Wz,
                                 (const float4*)Wh);

    dim3 ggrid(Hc / 64, (Bc * Tc) / BM);   // (16, 64)
    gemm_mma_kernel<<<ggrid, 512, SMEM_TOTAL>>>(bz, bh);

    scan_chunks_kernel<<<(NCHUNK * BHc / 2) / 256, 256>>>();
    scan_combine_kernel<<<(BHc * 32) / 256, 256>>>(h0);
    scan_final_kernel<<<(NCHUNK * BHc / 2) / 256, 256>>>(out);
}

// round 10
// speedup vs baseline: 1.2285x; 1.0619x over previous
#include <cuda_runtime.h>
#include <cuda_bf16.h>
#include <math.h>
#include <stdint.h>

// ---------------- problem dims -------------------------------------------
#define Bc 4
#define Tc 4096
#define Dc 1024
#define Hc 1024
#define BHc (Bc * Hc)
#define NCHUNK 128
#define CLEN (Tc / NCHUNK)       // 32

// ---------------- GEMM geometry ------------------------------------------
// CTA tile 128(M) x 128(N), 256 threads (8 warps), warp tile 64M x 32N.
// 2 CTAs/SM (96KB smem each) -> independent barrier domains keep the tensor
// pipe busy across tile boundaries. N rows interleave [Wz 16 | Wh 16] per
// 32-row j-block. K tile 64 bf16; 48 tiles (hi*hi | lo*hi | hi*lo).
#define BM 128
#define BN 128
#define NTILES 48
#define STAGES 3
#define A_BYTES (BM * 128)       // 16384
#define B_BYTES (BN * 128)       // 16384
#define STAGE_BYTES (A_BYTES + B_BYTES)   // 32768
#define SMEM_TOTAL (STAGES * STAGE_BYTES) // 98304 per CTA

// ---------------- scratch globals ----------------------------------------
__device__ __align__(1024) __nv_bfloat16 gx_hi[(size_t)Bc * Tc * Dc];
__device__ __align__(1024) __nv_bfloat16 gx_lo[(size_t)Bc * Tc * Dc];
__device__ __align__(1024) __nv_bfloat16 gw_hi[2048 * 1024];   // [Wz;Wh]
__device__ __align__(1024) __nv_bfloat16 gw_lo[2048 * 1024];
__device__ float2 g_lcv[(size_t)Bc * Tc * Hc];                 // (lc, lv)
__device__ float g_A[NCHUNK * BHc];
__device__ float g_R[NCHUNK * BHc];
__device__ float g_hin[NCHUNK * BHc];

// ---------------- PTX helpers --------------------------------------------
__device__ __forceinline__ uint32_t smem_u32(const void* p) {
    uint32_t a;
    asm("{ .reg .u64 t; cvta.to.shared.u64 t, %1; cvt.u32.u64 %0, t; }"
        : "=r"(a) : "l"(p));
    return a;
}
__device__ __forceinline__ void cp_async16(uint32_t dst, const void* src) {
    asm volatile("cp.async.cg.shared.global [%0], [%1], 16;"
                 :: "r"(dst), "l"(src) : "memory");
}
#define CP_COMMIT() asm volatile("cp.async.commit_group;" ::: "memory")
#define CP_WAIT_1() asm volatile("cp.async.wait_group 1;" ::: "memory")

#define LDSM_X4(r0, r1, r2, r3, addr) \
    asm volatile("ldmatrix.sync.aligned.m8n8.x4.shared.b16 {%0,%1,%2,%3}, [%4];" \
                 : "=r"(r0), "=r"(r1), "=r"(r2), "=r"(r3) : "r"(addr))

__device__ __forceinline__ void mma_bf16(float* c, const uint32_t* a,
                                         const uint32_t* b) {
    asm volatile(
        "mma.sync.aligned.m16n8k16.row.col.f32.bf16.bf16.f32 "
        "{%0,%1,%2,%3}, {%4,%5,%6,%7}, {%8,%9}, {%0,%1,%2,%3};"
        : "+f"(c[0]), "+f"(c[1]), "+f"(c[2]), "+f"(c[3])
        : "r"(a[0]), "r"(a[1]), "r"(a[2]), "r"(a[3]), "r"(b[0]), "r"(b[1]));
}

// ---------------- math helpers -------------------------------------------
__device__ __forceinline__ float softplus_f(float u) {
    return fmaxf(u, 0.f) + __logf(1.f + __expf(-fabsf(u)));
}
__device__ __forceinline__ float log_g_f(float v) {
    return (v >= 0.f) ? __logf(v + 0.5f) : -softplus_f(-v);
}
__device__ __forceinline__ float logaddexp_f(float a, float b) {
    float m = fmaxf(a, b);
    if (m == -INFINITY) return -INFINITY;
    return m + __logf(1.f + __expf(-fabsf(a - b)));
}
// lc = -softplus(k), lsig = -softplus(-k); share log1p(e^-|k|).
__device__ __forceinline__ void lc_lsig(float k, float& lc, float& lsig) {
    float L = __logf(1.f + __expf(-fabsf(k)));
    lc   = -fmaxf(k, 0.f)  - L;
    lsig = -fmaxf(-k, 0.f) - L;
}

// ===========================================================================
// merged bf16 split kernel: x (4,194,304 float4) then [Wz;Wh] (524,288 float4)
// ===========================================================================
__global__ void split_kernel(const float4* __restrict__ x,
                             const float4* __restrict__ Wz,
                             const float4* __restrict__ Wh)
{
    int i = blockIdx.x * blockDim.x + threadIdx.x;   // < 4718592
    float4 v;
    uint2 *dhi, *dlo;
    if (i < 4194304) {
        v = x[i];
        dhi = (uint2*)gx_hi + i;
        dlo = (uint2*)gx_lo + i;
    } else {
        int j = i - 4194304;                          // 0..524287
        v = (j < 262144) ? Wz[j] : Wh[j - 262144];
        dhi = (uint2*)gw_hi + j;
        dlo = (uint2*)gw_lo + j;
    }
    union { __nv_bfloat16 b[4]; uint2 u; } ph, pl;
    ph.b[0] = __float2bfloat16_rn(v.x); ph.b[1] = __float2bfloat16_rn(v.y);
    ph.b[2] = __float2bfloat16_rn(v.z); ph.b[3] = __float2bfloat16_rn(v.w);
    pl.b[0] = __float2bfloat16_rn(v.x - __bfloat162float(ph.b[0]));
    pl.b[1] = __float2bfloat16_rn(v.y - __bfloat162float(ph.b[1]));
    pl.b[2] = __float2bfloat16_rn(v.z - __bfloat162float(ph.b[2]));
    pl.b[3] = __float2bfloat16_rn(v.w - __bfloat162float(ph.b[3]));
    *dhi = ph.u;
    *dlo = pl.u;
}

// ===========================================================================
// HMMA GEMM + fused log-space epilogue. 256 threads, 8 warps,
// warp tile 64M x 32N. 3-stage cp.async pipeline, 2 CTAs/SM.
// B-tile row r (0..127): j = r>>5 selects the warp-column's 16-wide h block,
// w = r&31: w<16 -> Wz row (n0*64 + j*16 + w), w>=16 -> Wh row (same h).
// ===========================================================================
__device__ __forceinline__ void load_tile(
    int kt, uint32_t sbase, int m0, int n0, int tid)
{
    int phase = kt >> 4;
    int kk = (kt & 15) << 6;
    const __nv_bfloat16* A = (phase == 1) ? gx_lo : gx_hi;
    const __nv_bfloat16* B = (phase == 2) ? gw_lo : gw_hi;
    uint32_t bB = sbase + A_BYTES;
#pragma unroll
    for (int i = 0; i < 4; i++) {           // A: 128 rows x 8 chunks
        int idx = i * 256 + tid;
        int r = idx >> 3, c = idx & 7;
        uint32_t dst = sbase + r * 128 + ((c ^ (r & 7)) << 4);
        cp_async16(dst, A + (((size_t)(m0 + r)) << 10) + kk + (c << 3));
    }
#pragma unroll
    for (int i = 0; i < 4; i++) {           // B: 128 rows x 8 chunks
        int idx = i * 256 + tid;
        int r = idx >> 3, c = idx & 7;
        int j = r >> 5, w = r & 31;
        int grow = (w < 16) ? (n0 * 64 + j * 16 + w)
                            : (1024 + n0 * 64 + j * 16 + (w - 16));
        uint32_t dst = bB + r * 128 + ((c ^ (r & 7)) << 4);
        cp_async16(dst, B + (((size_t)grow) << 10) + kk + (c << 3));
    }
}

__global__ void __launch_bounds__(256, 2) gemm_mma_kernel(
    const float* __restrict__ bz_g, const float* __restrict__ bh_g)
{
    extern __shared__ __align__(1024) char sm[];
    const uint32_t smem_base = smem_u32(sm);
    const int tid = threadIdx.x;
    const int lane = tid & 31;
    const int wid = tid >> 5;
    const int warp_m = wid >> 2;       // 0..1 : 64-row M half
    const int warp_j = wid & 3;        // 0..3 : 32-row N block (16 h)
    const int n0 = blockIdx.x;         // 0..15
    const int m0 = blockIdx.y * BM;

    float acc[4][4][4];
#pragma unroll
    for (int a = 0; a < 4; a++)
#pragma unroll
        for (int b = 0; b < 4; b++)
#pragma unroll
            for (int c = 0; c < 4; c++) acc[a][b][c] = 0.f;

    load_tile(0, smem_base + 0 * STAGE_BYTES, m0, n0, tid); CP_COMMIT();
    load_tile(1, smem_base + 1 * STAGE_BYTES, m0, n0, tid); CP_COMMIT();

    const int a_row = lane & 15;       // m within 16-tile
    const int a_ch  = lane >> 4;       // k half
    const int b_row = lane & 7;        // n within 8-tile
    const int b_kh  = (lane >> 3) & 1; // k half
    const int b_td  = lane >> 4;       // n8 tile within pair

    int sc = 0, sl = 2;                // compute stage, load stage
    for (int kt = 0; kt < NTILES; ++kt) {
        CP_WAIT_1();                   // tile kt resident (this thread's part)
        __syncthreads();               // visible CTA-wide; compute kt-1 done
        if (kt + 2 < NTILES)
            load_tile(kt + 2, smem_base + sl * STAGE_BYTES, m0, n0, tid);
        CP_COMMIT();                   // empty group at tail keeps accounting
        if (++sl == STAGES) sl = 0;

        const uint32_t aB = smem_base + sc * STAGE_BYTES;
        const uint32_t bB = aB + A_BYTES;
        if (++sc == STAGES) sc = 0;
#pragma unroll
        for (int ks = 0; ks < 4; ks++) {
            uint32_t af[4][4];
#pragma unroll
            for (int mt = 0; mt < 4; mt++) {
                int r = warp_m * 64 + mt * 16 + a_row;
                int ch = (ks * 2 + a_ch) ^ (r & 7);
                LDSM_X4(af[mt][0], af[mt][1], af[mt][2], af[mt][3],
                        aB + r * 128 + ch * 16);
            }
            uint32_t bf[4][2];
#pragma unroll
            for (int tp = 0; tp < 2; tp++) {
                int r = warp_j * 32 + tp * 16 + b_td * 8 + b_row;
                int ch = (ks * 2 + b_kh) ^ (r & 7);
                LDSM_X4(bf[tp * 2][0], bf[tp * 2][1],
                        bf[tp * 2 + 1][0], bf[tp * 2 + 1][1],
                        bB + r * 128 + ch * 16);
            }
#pragma unroll
            for (int mt = 0; mt < 4; mt++)
#pragma unroll
                for (int t = 0; t < 4; t++)
                    mma_bf16(acc[mt][t], af[mt], bf[t]);
        }
    }

    // ---------------- fused epilogue (in-register) ------------------------
    // t = 0..1 hold k, t = 2..3 hold h~ for the same h coordinates.
    const int gr = lane >> 2;            // 0..7  (row in m16 tile)
    const int gc = (lane & 3) << 1;      // 0,2,4,6 (col pair)
#pragma unroll
    for (int t = 0; t < 2; t++) {
        int h = n0 * 64 + warp_j * 16 + t * 8 + gc;
        float bz0 = __ldg(bz_g + h),     bz1 = __ldg(bz_g + h + 1);
        float bh0 = __ldg(bh_g + h),     bh1 = __ldg(bh_g + h + 1);
#pragma unroll
        for (int mt = 0; mt < 4; mt++) {
            int r0 = m0 + warp_m * 64 + mt * 16 + gr;
            const float* ck = acc[mt][t];
            const float* ch = acc[mt][t + 2];
#pragma unroll
            for (int rr = 0; rr < 2; rr++) {
                float k0 = ck[rr * 2 + 0] + bz0;
                float k1 = ck[rr * 2 + 1] + bz1;
                float t0 = ch[rr * 2 + 0] + bh0;
                float t1 = ch[rr * 2 + 1] + bh1;
                float4 o;
                float ls0, ls1;
                lc_lsig(k0, o.x, ls0);
                lc_lsig(k1, o.z, ls1);
                o.y = ls0 + log_g_f(t0);
                o.w = ls1 + log_g_f(t1);
                *(float4*)((float*)g_lcv +
                           (((size_t)(r0 + rr * 8)) * Hc + h) * 2) = o;
            }
        }
    }
}

// ===========================================================================
// chunked parallel scan (log-space):  lh <- logaddexp(lh + lc, lv)
// 4 h-adjacent chains per thread, 2 independent float4 loads per step.
// ===========================================================================
__global__ void scan_chunks_kernel()
{
    int g = blockIdx.x * blockDim.x + threadIdx.x;   // < NCHUNK * BHc / 4
    int p = g & (BHc / 4 - 1);
    int c = g >> 10;
    int b = p >> 8;
    int h = (p & 255) << 2;
    size_t base = ((size_t)b * Tc + (size_t)c * CLEN) * Hc + h;
    float A0 = 0.f, R0 = -INFINITY, A1 = 0.f, R1 = -INFINITY;
    float A2 = 0.f, R2 = -INFINITY, A3 = 0.f, R3 = -INFINITY;
#pragma unroll 4
    for (int t = 0; t < CLEN; t++) {
        float4 u = *(const float4*)&g_lcv[base];
        float4 v = *(const float4*)&g_lcv[base + 2];
        base += Hc;
        R0 = logaddexp_f(R0 + u.x, u.y); A0 += u.x;
        R1 = logaddexp_f(R1 + u.z, u.w); A1 += u.z;
        R2 = logaddexp_f(R2 + v.x, v.y); A2 += v.x;
        R3 = logaddexp_f(R3 + v.z, v.w); A3 += v.z;
    }
    int idx = c * BHc + b * Hc + h;
    g_A[idx] = A0; g_A[idx + 1] = A1; g_A[idx + 2] = A2; g_A[idx + 3] = A3;
    g_R[idx] = R0; g_R[idx + 1] = R1; g_R[idx + 2] = R2; g_R[idx + 3] = R3;
}

// warp-parallel combine: 1 warp per chain; lane handles chunks 4L..4L+3;
// compose(P then Q) = (P.A + Q.A, logaddexp(P.R + Q.A, Q.R)).
__global__ void scan_combine_kernel(const float* __restrict__ h0)
{
    int gt = blockIdx.x * blockDim.x + threadIdx.x;
    int w = gt >> 5;                   // chain id < 4096
    int lane = gt & 31;
    float lh0 = log_g_f(__ldg(h0 + w));
    int i0 = (lane * 4) * BHc + w;
    float Al[4], Rl[4];
#pragma unroll
    for (int k = 0; k < 4; k++) {
        Al[k] = g_A[i0 + k * BHc];
        Rl[k] = g_R[i0 + k * BHc];
    }
    float Ai = Al[0], Ri = Rl[0];
#pragma unroll
    for (int k = 1; k < 4; k++) {
        Ri = logaddexp_f(Ri + Al[k], Rl[k]);
        Ai = Ai + Al[k];
    }
#pragma unroll
    for (int d = 1; d < 32; d <<= 1) {
        float Au = __shfl_up_sync(0xFFFFFFFFu, Ai, d);
        float Ru = __shfl_up_sync(0xFFFFFFFFu, Ri, d);
        if (lane >= d) {
            Ri = logaddexp_f(Ru + Ai, Ri);
            Ai = Au + Ai;
        }
    }
    float Ae = __shfl_up_sync(0xFFFFFFFFu, Ai, 1);
    float Re = __shfl_up_sync(0xFFFFFFFFu, Ri, 1);
    if (lane == 0) { Ae = 0.f; Re = -INFINITY; }
#pragma unroll
    for (int k = 0; k < 4; k++) {
        g_hin[i0 + k * BHc] = logaddexp_f(Ae + lh0, Re);
        Re = logaddexp_f(Re + Al[k], Rl[k]);
        Ae = Ae + Al[k];
    }
}

__global__ void scan_final_kernel(float* __restrict__ out)
{
    int g = blockIdx.x * blockDim.x + threadIdx.x;   // < NCHUNK * BHc / 4
    int p = g & (BHc / 4 - 1);
    int c = g >> 10;
    int b = p >> 8;
    int h = (p & 255) << 2;
    size_t base = ((size_t)b * Tc + (size_t)c * CLEN) * Hc + h;
    int idx = c * BHc + b * Hc + h;
    float lh0 = g_hin[idx],     lh1 = g_hin[idx + 1];
    float lh2 = g_hin[idx + 2], lh3 = g_hin[idx + 3];
#pragma unroll 4
    for (int t = 0; t < CLEN; t++) {
        float4 u = *(const float4*)&g_lcv[base];
        float4 v = *(const float4*)&g_lcv[base + 2];
        lh0 = logaddexp_f(lh0 + u.x, u.y);
        lh1 = logaddexp_f(lh1 + u.z, u.w);
        lh2 = logaddexp_f(lh2 + v.x, v.y);
        lh3 = logaddexp_f(lh3 + v.z, v.w);
        float4 o;
        o.x = __expf(lh0); o.y = __expf(lh1);
        o.z = __expf(lh2); o.w = __expf(lh3);
        *(float4*)&out[base] = o;
        base += Hc;
    }
}

// ===========================================================================
extern "C" void kernel_launch(void* const* d_in, const int* in_sizes, int n_in,
                              void* d_out, int out_size)
{
    const float* x  = (const float*)d_in[0];
    const float* h0 = (const float*)d_in[1];
    const float* Wz = (const float*)d_in[2];
    const float* bz = (const float*)d_in[3];
    const float* Wh = (const float*)d_in[4];
    const float* bh = (const float*)d_in[5];
    float* out = (float*)d_out;

    cudaFuncSetAttribute(gemm_mma_kernel,
                         cudaFuncAttributeMaxDynamicSharedMemorySize, SMEM_TOTAL);

    split_kernel<<<18432, 256>>>((const float4*)x, (const float4*)Wz,
                                 (const float4*)Wh);

    dim3 ggrid(Hc / 64, (Bc * Tc) / BM);   // (16, 128)
    gemm_mma_kernel<<<ggrid, 256, SMEM_TOTAL>>>(bz, bh);

    scan_chunks_kernel<<<(NCHUNK * BHc / 4) / 256, 256>>>();
    scan_combine_kernel<<<(BHc * 32) / 256, 256>>>(h0);
    scan_final_kernel<<<(NCHUNK * BHc / 4) / 256, 256>>>(out);
}

// round 11
// speedup vs baseline: 1.6593x; 1.3507x over previous
#include <cuda_runtime.h>
#include <cuda_bf16.h>
#include <math.h>
#include <stdint.h>

// ---------------- problem dims -------------------------------------------
#define Bc 4
#define Tc 4096
#define Dc 1024
#define Hc 1024
#define BHc (Bc * Hc)
#define NCHUNK 128
#define CLEN (Tc / NCHUNK)       // 32

// ---------------- GEMM geometry ------------------------------------------
// TF32 single-pass GEMM. CTA tile 128(M) x 128(N), 256 threads (8 warps),
// warp tile 64M x 32N, 2 CTAs/SM, 3-stage cp.async pipeline.
// K tile = 32 f32 (128B rows, same swizzle/ldmatrix geometry as bf16 k64).
// N rows interleave [Wz 16 | Wh 16] per 32-row j-block.
#define BM 128
#define BN 128
#define NTILES 32                // K = 1024
#define STAGES 3
#define A_BYTES (BM * 128)       // 16384
#define B_BYTES (BN * 128)       // 16384
#define STAGE_BYTES (A_BYTES + B_BYTES)   // 32768
#define SMEM_TOTAL (STAGES * STAGE_BYTES) // 98304 per CTA

// ---------------- scratch globals ----------------------------------------
__device__ __align__(1024) float gx[(size_t)Bc * Tc * Dc];     // rna(tf32) x
__device__ __align__(1024) float gw[2048 * 1024];              // rna [Wz;Wh]
__device__ float2 g_lcv[(size_t)Bc * Tc * Hc];                 // (lc, lv)
__device__ float g_A[NCHUNK * BHc];
__device__ float g_R[NCHUNK * BHc];
__device__ float g_hin[NCHUNK * BHc];

// ---------------- PTX helpers --------------------------------------------
__device__ __forceinline__ uint32_t smem_u32(const void* p) {
    uint32_t a;
    asm("{ .reg .u64 t; cvta.to.shared.u64 t, %1; cvt.u32.u64 %0, t; }"
        : "=r"(a) : "l"(p));
    return a;
}
__device__ __forceinline__ void cp_async16(uint32_t dst, const void* src) {
    asm volatile("cp.async.cg.shared.global [%0], [%1], 16;"
                 :: "r"(dst), "l"(src) : "memory");
}
#define CP_COMMIT() asm volatile("cp.async.commit_group;" ::: "memory")
#define CP_WAIT_1() asm volatile("cp.async.wait_group 1;" ::: "memory")

#define LDSM_X4(r0, r1, r2, r3, addr) \
    asm volatile("ldmatrix.sync.aligned.m8n8.x4.shared.b16 {%0,%1,%2,%3}, [%4];" \
                 : "=r"(r0), "=r"(r1), "=r"(r2), "=r"(r3) : "r"(addr))

__device__ __forceinline__ void mma_tf32(float* c, const uint32_t* a,
                                         const uint32_t* b) {
    asm volatile(
        "mma.sync.aligned.m16n8k8.row.col.f32.tf32.tf32.f32 "
        "{%0,%1,%2,%3}, {%4,%5,%6,%7}, {%8,%9}, {%0,%1,%2,%3};"
        : "+f"(c[0]), "+f"(c[1]), "+f"(c[2]), "+f"(c[3])
        : "r"(a[0]), "r"(a[1]), "r"(a[2]), "r"(a[3]), "r"(b[0]), "r"(b[1]));
}
__device__ __forceinline__ float rna_tf32(float v) {
    uint32_t r;
    asm("cvt.rna.tf32.f32 %0, %1;" : "=r"(r) : "f"(v));
    return __uint_as_float(r);
}

// ---------------- math helpers -------------------------------------------
__device__ __forceinline__ float softplus_f(float u) {
    return fmaxf(u, 0.f) + __logf(1.f + __expf(-fabsf(u)));
}
__device__ __forceinline__ float log_g_f(float v) {
    return (v >= 0.f) ? __logf(v + 0.5f) : -softplus_f(-v);
}
__device__ __forceinline__ float logaddexp_f(float a, float b) {
    float m = fmaxf(a, b);
    if (m == -INFINITY) return -INFINITY;
    return m + __logf(1.f + __expf(-fabsf(a - b)));
}
// lc = -softplus(k), lsig = -softplus(-k); share log1p(e^-|k|).
__device__ __forceinline__ void lc_lsig(float k, float& lc, float& lsig) {
    float L = __logf(1.f + __expf(-fabsf(k)));
    lc   = -fmaxf(k, 0.f)  - L;
    lsig = -fmaxf(-k, 0.f) - L;
}

// ===========================================================================
// rna(tf32) rounding kernel: x (4,194,304 float4) then [Wz;Wh] (524,288)
// Pre-rounding removes the truncation bias the tf32 mma would otherwise add.
// ===========================================================================
__global__ void round_kernel(const float4* __restrict__ x,
                             const float4* __restrict__ Wz,
                             const float4* __restrict__ Wh)
{
    int i = blockIdx.x * blockDim.x + threadIdx.x;   // < 4718592
    float4 v;
    float4* dst;
    if (i < 4194304) {
        v = x[i];
        dst = (float4*)gx + i;
    } else {
        int j = i - 4194304;                          // 0..524287
        v = (j < 262144) ? Wz[j] : Wh[j - 262144];
        dst = (float4*)gw + j;
    }
    float4 o;
    o.x = rna_tf32(v.x); o.y = rna_tf32(v.y);
    o.z = rna_tf32(v.z); o.w = rna_tf32(v.w);
    *dst = o;
}

// ===========================================================================
// TF32 MMA GEMM + fused log-space epilogue.
// A tf32 m16k8 fragment viewed as b16 pairs == bf16 m16k16 fragment, so the
// ldmatrix addressing and swizzle are identical to the bf16 kernel.
// B-tile row r (0..127): j = r>>5 selects the warp-column's 16-wide h block,
// w = r&31: w<16 -> Wz row (n0*64 + j*16 + w), w>=16 -> Wh row (same h).
// ===========================================================================
__device__ __forceinline__ void load_tile(
    int kt, uint32_t sbase, int m0, int n0, int tid)
{
    int kk = kt << 5;                       // f32 column offset
    uint32_t bB = sbase + A_BYTES;
#pragma unroll
    for (int i = 0; i < 4; i++) {           // A: 128 rows x 8 chunks
        int idx = i * 256 + tid;
        int r = idx >> 3, c = idx & 7;
        uint32_t dst = sbase + r * 128 + ((c ^ (r & 7)) << 4);
        cp_async16(dst, gx + (((size_t)(m0 + r)) << 10) + kk + (c << 2));
    }
#pragma unroll
    for (int i = 0; i < 4; i++) {           // B: 128 rows x 8 chunks
        int idx = i * 256 + tid;
        int r = idx >> 3, c = idx & 7;
        int j = r >> 5, w = r & 31;
        int grow = (w < 16) ? (n0 * 64 + j * 16 + w)
                            : (1024 + n0 * 64 + j * 16 + (w - 16));
        uint32_t dst = bB + r * 128 + ((c ^ (r & 7)) << 4);
        cp_async16(dst, gw + (((size_t)grow) << 10) + kk + (c << 2));
    }
}

__global__ void __launch_bounds__(256, 2) gemm_mma_kernel(
    const float* __restrict__ bz_g, const float* __restrict__ bh_g)
{
    extern __shared__ __align__(1024) char sm[];
    const uint32_t smem_base = smem_u32(sm);
    const int tid = threadIdx.x;
    const int lane = tid & 31;
    const int wid = tid >> 5;
    const int warp_m = wid >> 2;       // 0..1 : 64-row M half
    const int warp_j = wid & 3;        // 0..3 : 32-row N block (16 h)
    const int n0 = blockIdx.x;         // 0..15
    const int m0 = blockIdx.y * BM;

    float acc[4][4][4];
#pragma unroll
    for (int a = 0; a < 4; a++)
#pragma unroll
        for (int b = 0; b < 4; b++)
#pragma unroll
            for (int c = 0; c < 4; c++) acc[a][b][c] = 0.f;

    load_tile(0, smem_base + 0 * STAGE_BYTES, m0, n0, tid); CP_COMMIT();
    load_tile(1, smem_base + 1 * STAGE_BYTES, m0, n0, tid); CP_COMMIT();

    const int a_row = lane & 15;       // m within 16-tile
    const int a_ch  = lane >> 4;       // k half (chunk select)
    const int b_row = lane & 7;        // n within 8-tile
    const int b_kh  = (lane >> 3) & 1; // k half (chunk select)
    const int b_td  = lane >> 4;       // n8 tile within pair

    int sc = 0, sl = 2;                // compute stage, load stage
    for (int kt = 0; kt < NTILES; ++kt) {
        CP_WAIT_1();                   // tile kt resident (this thread's part)
        __syncthreads();               // visible CTA-wide; compute kt-1 done
        if (kt + 2 < NTILES)
            load_tile(kt + 2, smem_base + sl * STAGE_BYTES, m0, n0, tid);
        CP_COMMIT();                   // empty group at tail keeps accounting
        if (++sl == STAGES) sl = 0;

        const uint32_t aB = smem_base + sc * STAGE_BYTES;
        const uint32_t bB = aB + A_BYTES;
        if (++sc == STAGES) sc = 0;
#pragma unroll
        for (int ks = 0; ks < 4; ks++) {   // 4 k8 steps per 32-f32 tile
            uint32_t af[4][4];
#pragma unroll
            for (int mt = 0; mt < 4; mt++) {
                int r = warp_m * 64 + mt * 16 + a_row;
                int ch = (ks * 2 + a_ch) ^ (r & 7);
                LDSM_X4(af[mt][0], af[mt][1], af[mt][2], af[mt][3],
                        aB + r * 128 + ch * 16);
            }
            uint32_t bf[4][2];
#pragma unroll
            for (int tp = 0; tp < 2; tp++) {
                int r = warp_j * 32 + tp * 16 + b_td * 8 + b_row;
                int ch = (ks * 2 + b_kh) ^ (r & 7);
                LDSM_X4(bf[tp * 2][0], bf[tp * 2][1],
                        bf[tp * 2 + 1][0], bf[tp * 2 + 1][1],
                        bB + r * 128 + ch * 16);
            }
#pragma unroll
            for (int mt = 0; mt < 4; mt++)
#pragma unroll
                for (int t = 0; t < 4; t++)
                    mma_tf32(acc[mt][t], af[mt], bf[t]);
        }
    }

    // ---------------- fused epilogue (in-register) ------------------------
    // t = 0..1 hold k, t = 2..3 hold h~ for the same h coordinates.
    const int gr = lane >> 2;            // 0..7  (row in m16 tile)
    const int gc = (lane & 3) << 1;      // 0,2,4,6 (col pair)
#pragma unroll
    for (int t = 0; t < 2; t++) {
        int h = n0 * 64 + warp_j * 16 + t * 8 + gc;
        float bz0 = __ldg(bz_g + h),     bz1 = __ldg(bz_g + h + 1);
        float bh0 = __ldg(bh_g + h),     bh1 = __ldg(bh_g + h + 1);
#pragma unroll
        for (int mt = 0; mt < 4; mt++) {
            int r0 = m0 + warp_m * 64 + mt * 16 + gr;
            const float* ck = acc[mt][t];
            const float* ch = acc[mt][t + 2];
#pragma unroll
            for (int rr = 0; rr < 2; rr++) {
                float k0 = ck[rr * 2 + 0] + bz0;
                float k1 = ck[rr * 2 + 1] + bz1;
                float t0 = ch[rr * 2 + 0] + bh0;
                float t1 = ch[rr * 2 + 1] + bh1;
                float4 o;
                float ls0, ls1;
                lc_lsig(k0, o.x, ls0);
                lc_lsig(k1, o.z, ls1);
                o.y = ls0 + log_g_f(t0);
                o.w = ls1 + log_g_f(t1);
                *(float4*)((float*)g_lcv +
                           (((size_t)(r0 + rr * 8)) * Hc + h) * 2) = o;
            }
        }
    }
}

// ===========================================================================
// chunked parallel scan (log-space):  lh <- logaddexp(lh + lc, lv)
// 4 h-adjacent chains per thread, 2 independent float4 loads per step.
// ===========================================================================
__global__ void scan_chunks_kernel()
{
    int g = blockIdx.x * blockDim.x + threadIdx.x;   // < NCHUNK * BHc / 4
    int p = g & (BHc / 4 - 1);
    int c = g >> 10;
    int b = p >> 8;
    int h = (p & 255) << 2;
    size_t base = ((size_t)b * Tc + (size_t)c * CLEN) * Hc + h;
    float A0 = 0.f, R0 = -INFINITY, A1 = 0.f, R1 = -INFINITY;
    float A2 = 0.f, R2 = -INFINITY, A3 = 0.f, R3 = -INFINITY;
#pragma unroll 4
    for (int t = 0; t < CLEN; t++) {
        float4 u = *(const float4*)&g_lcv[base];
        float4 v = *(const float4*)&g_lcv[base + 2];
        base += Hc;
        R0 = logaddexp_f(R0 + u.x, u.y); A0 += u.x;
        R1 = logaddexp_f(R1 + u.z, u.w); A1 += u.z;
        R2 = logaddexp_f(R2 + v.x, v.y); A2 += v.x;
        R3 = logaddexp_f(R3 + v.z, v.w); A3 += v.z;
    }
    int idx = c * BHc + b * Hc + h;
    g_A[idx] = A0; g_A[idx + 1] = A1; g_A[idx + 2] = A2; g_A[idx + 3] = A3;
    g_R[idx] = R0; g_R[idx + 1] = R1; g_R[idx + 2] = R2; g_R[idx + 3] = R3;
}

// warp-parallel combine: 1 warp per chain; lane handles chunks 4L..4L+3;
// compose(P then Q) = (P.A + Q.A, logaddexp(P.R + Q.A, Q.R)).
__global__ void scan_combine_kernel(const float* __restrict__ h0)
{
    int gt = blockIdx.x * blockDim.x + threadIdx.x;
    int w = gt >> 5;                   // chain id < 4096
    int lane = gt & 31;
    float lh0 = log_g_f(__ldg(h0 + w));
    int i0 = (lane * 4) * BHc + w;
    float Al[4], Rl[4];
#pragma unroll
    for (int k = 0; k < 4; k++) {
        Al[k] = g_A[i0 + k * BHc];
        Rl[k] = g_R[i0 + k * BHc];
    }
    float Ai = Al[0], Ri = Rl[0];
#pragma unroll
    for (int k = 1; k < 4; k++) {
        Ri = logaddexp_f(Ri + Al[k], Rl[k]);
        Ai = Ai + Al[k];
    }
#pragma unroll
    for (int d = 1; d < 32; d <<= 1) {
        float Au = __shfl_up_sync(0xFFFFFFFFu, Ai, d);
        float Ru = __shfl_up_sync(0xFFFFFFFFu, Ri, d);
        if (lane >= d) {
            Ri = logaddexp_f(Ru + Ai, Ri);
            Ai = Au + Ai;
        }
    }
    float Ae = __shfl_up_sync(0xFFFFFFFFu, Ai, 1);
    float Re = __shfl_up_sync(0xFFFFFFFFu, Ri, 1);
    if (lane == 0) { Ae = 0.f; Re = -INFINITY; }
#pragma unroll
    for (int k = 0; k < 4; k++) {
        g_hin[i0 + k * BHc] = logaddexp_f(Ae + lh0, Re);
        Re = logaddexp_f(Re + Al[k], Rl[k]);
        Ae = Ae + Al[k];
    }
}

__global__ void scan_final_kernel(float* __restrict__ out)
{
    int g = blockIdx.x * blockDim.x + threadIdx.x;   // < NCHUNK * BHc / 4
    int p = g & (BHc / 4 - 1);
    int c = g >> 10;
    int b = p >> 8;
    int h = (p & 255) << 2;
    size_t base = ((size_t)b * Tc + (size_t)c * CLEN) * Hc + h;
    int idx = c * BHc + b * Hc + h;
    float lh0 = g_hin[idx],     lh1 = g_hin[idx + 1];
    float lh2 = g_hin[idx + 2], lh3 = g_hin[idx + 3];
#pragma unroll 4
    for (int t = 0; t < CLEN; t++) {
        float4 u = *(const float4*)&g_lcv[base];
        float4 v = *(const float4*)&g_lcv[base + 2];
        lh0 = logaddexp_f(lh0 + u.x, u.y);
        lh1 = logaddexp_f(lh1 + u.z, u.w);
        lh2 = logaddexp_f(lh2 + v.x, v.y);
        lh3 = logaddexp_f(lh3 + v.z, v.w);
        float4 o;
        o.x = __expf(lh0); o.y = __expf(lh1);
        o.z = __expf(lh2); o.w = __expf(lh3);
        *(float4*)&out[base] = o;
        base += Hc;
    }
}

// ===========================================================================
extern "C" void kernel_launch(void* const* d_in, const int* in_sizes, int n_in,
                              void* d_out, int out_size)
{
    const float* x  = (const float*)d_in[0];
    const float* h0 = (const float*)d_in[1];
    const float* Wz = (const float*)d_in[2];
    const float* bz = (const float*)d_in[3];
    const float* Wh = (const float*)d_in[4];
    const float* bh = (const float*)d_in[5];
    float* out = (float*)d_out;

    cudaFuncSetAttribute(gemm_mma_kernel,
                         cudaFuncAttributeMaxDynamicSharedMemorySize, SMEM_TOTAL);

    round_kernel<<<18432, 256>>>((const float4*)x, (const float4*)Wz,
                                 (const float4*)Wh);

    dim3 ggrid(Hc / 64, (Bc * Tc) / BM);   // (16, 128)
    gemm_mma_kernel<<<ggrid, 256, SMEM_TOTAL>>>(bz, bh);

    scan_chunks_kernel<<<(NCHUNK * BHc / 4) / 256, 256>>>();
    scan_combine_kernel<<<(BHc * 32) / 256, 256>>>(h0);
    scan_final_kernel<<<(NCHUNK * BHc / 4) / 256, 256>>>(out);
}

// round 12
// speedup vs baseline: 2.5390x; 1.5301x over previous
#include <cuda_runtime.h>
#include <cuda_fp16.h>
#include <math.h>
#include <stdint.h>

// ---------------- problem dims -------------------------------------------
#define Bc 4
#define Tc 4096
#define Dc 1024
#define Hc 1024
#define BHc (Bc * Hc)
#define NCHUNK 128
#define CLEN (Tc / NCHUNK)       // 32

// ---------------- GEMM geometry ------------------------------------------
// fp16 single-pass GEMM (10-bit mantissa == tf32 precision, half the mma
// instructions). CTA tile 128(M) x 128(N), 256 threads (8 warps), warp tile
// 64M x 32N, 2 CTAs/SM, 3-stage cp.async pipeline. K tile 64 fp16 (128B
// rows). N rows interleave [Wz 16 | Wh 16] per 32-row j-block.
#define BM 128
#define BN 128
#define NTILES 16                // K = 1024
#define STAGES 3
#define A_BYTES (BM * 128)       // 16384
#define B_BYTES (BN * 128)       // 16384
#define STAGE_BYTES (A_BYTES + B_BYTES)   // 32768
#define SMEM_TOTAL (STAGES * STAGE_BYTES) // 98304 per CTA

// ---------------- scratch globals ----------------------------------------
__device__ __align__(1024) __half gx[(size_t)Bc * Tc * Dc];    // fp16 x
__device__ __align__(1024) __half gw[2048 * 1024];             // fp16 [Wz;Wh]
__device__ float2 g_lcv[(size_t)Bc * Tc * Hc];                 // (lc, lv)
__device__ float g_A[NCHUNK * BHc];
__device__ float g_R[NCHUNK * BHc];
__device__ float g_hin[NCHUNK * BHc];

// ---------------- PTX helpers --------------------------------------------
__device__ __forceinline__ uint32_t smem_u32(const void* p) {
    uint32_t a;
    asm("{ .reg .u64 t; cvta.to.shared.u64 t, %1; cvt.u32.u64 %0, t; }"
        : "=r"(a) : "l"(p));
    return a;
}
__device__ __forceinline__ void cp_async16(uint32_t dst, const void* src) {
    asm volatile("cp.async.cg.shared.global [%0], [%1], 16;"
                 :: "r"(dst), "l"(src) : "memory");
}
#define CP_COMMIT() asm volatile("cp.async.commit_group;" ::: "memory")
#define CP_WAIT_1() asm volatile("cp.async.wait_group 1;" ::: "memory")

#define LDSM_X4(r0, r1, r2, r3, addr) \
    asm volatile("ldmatrix.sync.aligned.m8n8.x4.shared.b16 {%0,%1,%2,%3}, [%4];" \
                 : "=r"(r0), "=r"(r1), "=r"(r2), "=r"(r3) : "r"(addr))

__device__ __forceinline__ void mma_f16(float* c, const uint32_t* a,
                                        const uint32_t* b) {
    asm volatile(
        "mma.sync.aligned.m16n8k16.row.col.f32.f16.f16.f32 "
        "{%0,%1,%2,%3}, {%4,%5,%6,%7}, {%8,%9}, {%0,%1,%2,%3};"
        : "+f"(c[0]), "+f"(c[1]), "+f"(c[2]), "+f"(c[3])
        : "r"(a[0]), "r"(a[1]), "r"(a[2]), "r"(a[3]), "r"(b[0]), "r"(b[1]));
}

// ---------------- math helpers -------------------------------------------
__device__ __forceinline__ float softplus_f(float u) {
    return fmaxf(u, 0.f) + __logf(1.f + __expf(-fabsf(u)));
}
__device__ __forceinline__ float log_g_f(float v) {
    return (v >= 0.f) ? __logf(v + 0.5f) : -softplus_f(-v);
}
__device__ __forceinline__ float logaddexp_f(float a, float b) {
    float m = fmaxf(a, b);
    if (m == -INFINITY) return -INFINITY;
    return m + __logf(1.f + __expf(-fabsf(a - b)));
}
// lc = -softplus(k), lsig = -softplus(-k); share log1p(e^-|k|).
__device__ __forceinline__ void lc_lsig(float k, float& lc, float& lsig) {
    float L = __logf(1.f + __expf(-fabsf(k)));
    lc   = -fmaxf(k, 0.f)  - L;
    lsig = -fmaxf(-k, 0.f) - L;
}

// ===========================================================================
// fp16 convert kernel: x (4,194,304 float4) then [Wz;Wh] (524,288 float4)
// ===========================================================================
__global__ void cvt_kernel(const float4* __restrict__ x,
                           const float4* __restrict__ Wz,
                           const float4* __restrict__ Wh)
{
    int i = blockIdx.x * blockDim.x + threadIdx.x;   // < 4718592
    float4 v;
    uint2* dst;
    if (i < 4194304) {
        v = x[i];
        dst = (uint2*)gx + i;
    } else {
        int j = i - 4194304;                          // 0..524287
        v = (j < 262144) ? Wz[j] : Wh[j - 262144];
        dst = (uint2*)gw + j;
    }
    union { __half h[4]; uint2 u; } o;
    o.h[0] = __float2half_rn(v.x); o.h[1] = __float2half_rn(v.y);
    o.h[2] = __float2half_rn(v.z); o.h[3] = __float2half_rn(v.w);
    *dst = o.u;
}

// ===========================================================================
// fp16 MMA GEMM + fused log-space epilogue.
// B-tile row r (0..127): j = r>>5 selects the warp-column's 16-wide h block,
// w = r&31: w<16 -> Wz row (n0*64 + j*16 + w), w>=16 -> Wh row (same h).
// ===========================================================================
__device__ __forceinline__ void load_tile(
    int kt, uint32_t sbase, int m0, int n0, int tid)
{
    int kk = kt << 6;                       // fp16 column offset
    uint32_t bB = sbase + A_BYTES;
#pragma unroll
    for (int i = 0; i < 4; i++) {           // A: 128 rows x 8 chunks
        int idx = i * 256 + tid;
        int r = idx >> 3, c = idx & 7;
        uint32_t dst = sbase + r * 128 + ((c ^ (r & 7)) << 4);
        cp_async16(dst, gx + (((size_t)(m0 + r)) << 10) + kk + (c << 3));
    }
#pragma unroll
    for (int i = 0; i < 4; i++) {           // B: 128 rows x 8 chunks
        int idx = i * 256 + tid;
        int r = idx >> 3, c = idx & 7;
        int j = r >> 5, w = r & 31;
        int grow = (w < 16) ? (n0 * 64 + j * 16 + w)
                            : (1024 + n0 * 64 + j * 16 + (w - 16));
        uint32_t dst = bB + r * 128 + ((c ^ (r & 7)) << 4);
        cp_async16(dst, gw + (((size_t)grow) << 10) + kk + (c << 3));
    }
}

__global__ void __launch_bounds__(256, 2) gemm_mma_kernel(
    const float* __restrict__ bz_g, const float* __restrict__ bh_g)
{
    extern __shared__ __align__(1024) char sm[];
    const uint32_t smem_base = smem_u32(sm);
    const int tid = threadIdx.x;
    const int lane = tid & 31;
    const int wid = tid >> 5;
    const int warp_m = wid >> 2;       // 0..1 : 64-row M half
    const int warp_j = wid & 3;        // 0..3 : 32-row N block (16 h)
    const int n0 = blockIdx.x;         // 0..15
    const int m0 = blockIdx.y * BM;

    float acc[4][4][4];
#pragma unroll
    for (int a = 0; a < 4; a++)
#pragma unroll
        for (int b = 0; b < 4; b++)
#pragma unroll
            for (int c = 0; c < 4; c++) acc[a][b][c] = 0.f;

    load_tile(0, smem_base + 0 * STAGE_BYTES, m0, n0, tid); CP_COMMIT();
    load_tile(1, smem_base + 1 * STAGE_BYTES, m0, n0, tid); CP_COMMIT();

    const int a_row = lane & 15;       // m within 16-tile
    const int a_ch  = lane >> 4;       // k half (chunk select)
    const int b_row = lane & 7;        // n within 8-tile
    const int b_kh  = (lane >> 3) & 1; // k half (chunk select)
    const int b_td  = lane >> 4;       // n8 tile within pair

    int sc = 0, sl = 2;                // compute stage, load stage
    for (int kt = 0; kt < NTILES; ++kt) {
        CP_WAIT_1();                   // tile kt resident (this thread's part)
        __syncthreads();               // visible CTA-wide; compute kt-1 done
        if (kt + 2 < NTILES)
            load_tile(kt + 2, smem_base + sl * STAGE_BYTES, m0, n0, tid);
        CP_COMMIT();                   // empty group at tail keeps accounting
        if (++sl == STAGES) sl = 0;

        const uint32_t aB = smem_base + sc * STAGE_BYTES;
        const uint32_t bB = aB + A_BYTES;
        if (++sc == STAGES) sc = 0;
#pragma unroll
        for (int ks = 0; ks < 4; ks++) {   // 4 k16 steps per 64-fp16 tile
            uint32_t af[4][4];
#pragma unroll
            for (int mt = 0; mt < 4; mt++) {
                int r = warp_m * 64 + mt * 16 + a_row;
                int ch = (ks * 2 + a_ch) ^ (r & 7);
                LDSM_X4(af[mt][0], af[mt][1], af[mt][2], af[mt][3],
                        aB + r * 128 + ch * 16);
            }
            uint32_t bf[4][2];
#pragma unroll
            for (int tp = 0; tp < 2; tp++) {
                int r = warp_j * 32 + tp * 16 + b_td * 8 + b_row;
                int ch = (ks * 2 + b_kh) ^ (r & 7);
                LDSM_X4(bf[tp * 2][0], bf[tp * 2][1],
                        bf[tp * 2 + 1][0], bf[tp * 2 + 1][1],
                        bB + r * 128 + ch * 16);
            }
#pragma unroll
            for (int mt = 0; mt < 4; mt++)
#pragma unroll
                for (int t = 0; t < 4; t++)
                    mma_f16(acc[mt][t], af[mt], bf[t]);
        }
    }

    // ---------------- fused epilogue (in-register) ------------------------
    // t = 0..1 hold k, t = 2..3 hold h~ for the same h coordinates.
    const int gr = lane >> 2;            // 0..7  (row in m16 tile)
    const int gc = (lane & 3) << 1;      // 0,2,4,6 (col pair)
#pragma unroll
    for (int t = 0; t < 2; t++) {
        int h = n0 * 64 + warp_j * 16 + t * 8 + gc;
        float bz0 = __ldg(bz_g + h),     bz1 = __ldg(bz_g + h + 1);
        float bh0 = __ldg(bh_g + h),     bh1 = __ldg(bh_g + h + 1);
#pragma unroll
        for (int mt = 0; mt < 4; mt++) {
            int r0 = m0 + warp_m * 64 + mt * 16 + gr;
            const float* ck = acc[mt][t];
            const float* ch = acc[mt][t + 2];
#pragma unroll
            for (int rr = 0; rr < 2; rr++) {
                float k0 = ck[rr * 2 + 0] + bz0;
                float k1 = ck[rr * 2 + 1] + bz1;
                float t0 = ch[rr * 2 + 0] + bh0;
                float t1 = ch[rr * 2 + 1] + bh1;
                float4 o;
                float ls0, ls1;
                lc_lsig(k0, o.x, ls0);
                lc_lsig(k1, o.z, ls1);
                o.y = ls0 + log_g_f(t0);
                o.w = ls1 + log_g_f(t1);
                *(float4*)((float*)g_lcv +
                           (((size_t)(r0 + rr * 8)) * Hc + h) * 2) = o;
            }
        }
    }
}

// ===========================================================================
// chunked parallel scan (log-space):  lh <- logaddexp(lh + lc, lv)
// 4 h-adjacent chains per thread, 2 independent float4 loads per step.
// ===========================================================================
__global__ void scan_chunks_kernel()
{
    int g = blockIdx.x * blockDim.x + threadIdx.x;   // < NCHUNK * BHc / 4
    int p = g & (BHc / 4 - 1);
    int c = g >> 10;
    int b = p >> 8;
    int h = (p & 255) << 2;
    size_t base = ((size_t)b * Tc + (size_t)c * CLEN) * Hc + h;
    float A0 = 0.f, R0 = -INFINITY, A1 = 0.f, R1 = -INFINITY;
    float A2 = 0.f, R2 = -INFINITY, A3 = 0.f, R3 = -INFINITY;
#pragma unroll 4
    for (int t = 0; t < CLEN; t++) {
        float4 u = *(const float4*)&g_lcv[base];
        float4 v = *(const float4*)&g_lcv[base + 2];
        base += Hc;
        R0 = logaddexp_f(R0 + u.x, u.y); A0 += u.x;
        R1 = logaddexp_f(R1 + u.z, u.w); A1 += u.z;
        R2 = logaddexp_f(R2 + v.x, v.y); A2 += v.x;
        R3 = logaddexp_f(R3 + v.z, v.w); A3 += v.z;
    }
    int idx = c * BHc + b * Hc + h;
    g_A[idx] = A0; g_A[idx + 1] = A1; g_A[idx + 2] = A2; g_A[idx + 3] = A3;
    g_R[idx] = R0; g_R[idx + 1] = R1; g_R[idx + 2] = R2; g_R[idx + 3] = R3;
}

// warp-parallel combine: 1 warp per chain; lane handles chunks 4L..4L+3;
// compose(P then Q) = (P.A + Q.A, logaddexp(P.R + Q.A, Q.R)).
__global__ void scan_combine_kernel(const float* __restrict__ h0)
{
    int gt = blockIdx.x * blockDim.x + threadIdx.x;
    int w = gt >> 5;                   // chain id < 4096
    int lane = gt & 31;
    float lh0 = log_g_f(__ldg(h0 + w));
    int i0 = (lane * 4) * BHc + w;
    float Al[4], Rl[4];
#pragma unroll
    for (int k = 0; k < 4; k++) {
        Al[k] = g_A[i0 + k * BHc];
        Rl[k] = g_R[i0 + k * BHc];
    }
    float Ai = Al[0], Ri = Rl[0];
#pragma unroll
    for (int k = 1; k < 4; k++) {
        Ri = logaddexp_f(Ri + Al[k], Rl[k]);
        Ai = Ai + Al[k];
    }
#pragma unroll
    for (int d = 1; d < 32; d <<= 1) {
        float Au = __shfl_up_sync(0xFFFFFFFFu, Ai, d);
        float Ru = __shfl_up_sync(0xFFFFFFFFu, Ri, d);
        if (lane >= d) {
            Ri = logaddexp_f(Ru + Ai, Ri);
            Ai = Au + Ai;
        }
    }
    float Ae = __shfl_up_sync(0xFFFFFFFFu, Ai, 1);
    float Re = __shfl_up_sync(0xFFFFFFFFu, Ri, 1);
    if (lane == 0) { Ae = 0.f; Re = -INFINITY; }
#pragma unroll
    for (int k = 0; k < 4; k++) {
        g_hin[i0 + k * BHc] = logaddexp_f(Ae + lh0, Re);
        Re = logaddexp_f(Re + Al[k], Rl[k]);
        Ae = Ae + Al[k];
    }
}

__global__ void scan_final_kernel(float* __restrict__ out)
{
    int g = blockIdx.x * blockDim.x + threadIdx.x;   // < NCHUNK * BHc / 4
    int p = g & (BHc / 4 - 1);
    int c = g >> 10;
    int b = p >> 8;
    int h = (p & 255) << 2;
    size_t base = ((size_t)b * Tc + (size_t)c * CLEN) * Hc + h;
    int idx = c * BHc + b * Hc + h;
    float lh0 = g_hin[idx],     lh1 = g_hin[idx + 1];
    float lh2 = g_hin[idx + 2], lh3 = g_hin[idx + 3];
#pragma unroll 4
    for (int t = 0; t < CLEN; t++) {
        float4 u = *(const float4*)&g_lcv[base];
        float4 v = *(const float4*)&g_lcv[base + 2];
        lh0 = logaddexp_f(lh0 + u.x, u.y);
        lh1 = logaddexp_f(lh1 + u.z, u.w);
        lh2 = logaddexp_f(lh2 + v.x, v.y);
        lh3 = logaddexp_f(lh3 + v.z, v.w);
        float4 o;
        o.x = __expf(lh0); o.y = __expf(lh1);
        o.z = __expf(lh2); o.w = __expf(lh3);
        *(float4*)&out[base] = o;
        base += Hc;
    }
}

// ===========================================================================
extern "C" void kernel_launch(void* const* d_in, const int* in_sizes, int n_in,
                              void* d_out, int out_size)
{
    const float* x  = (const float*)d_in[0];
    const float* h0 = (const float*)d_in[1];
    const float* Wz = (const float*)d_in[2];
    const float* bz = (const float*)d_in[3];
    const float* Wh = (const float*)d_in[4];
    const float* bh = (const float*)d_in[5];
    float* out = (float*)d_out;

    cudaFuncSetAttribute(gemm_mma_kernel,
                         cudaFuncAttributeMaxDynamicSharedMemorySize, SMEM_TOTAL);

    cvt_kernel<<<18432, 256>>>((const float4*)x, (const float4*)Wz,
                               (const float4*)Wh);

    dim3 ggrid(Hc / 64, (Bc * Tc) / BM);   // (16, 128)
    gemm_mma_kernel<<<ggrid, 256, SMEM_TOTAL>>>(bz, bh);

    scan_chunks_kernel<<<(NCHUNK * BHc / 4) / 256, 256>>>();
    scan_combine_kernel<<<(BHc * 32) / 256, 256>>>(h0);
    scan_final_kernel<<<(NCHUNK * BHc / 4) / 256, 256>>>(out);
}

// round 13
// speedup vs baseline: 2.5784x; 1.0155x over previous
#include <cuda_runtime.h>
#include <cuda_fp16.h>
#include <math.h>
#include <stdint.h>

// ---------------- problem dims -------------------------------------------
#define Bc 4
#define Tc 4096
#define Dc 1024
#define Hc 1024
#define BHc (Bc * Hc)
#define NCHUNK 128
#define CLEN (Tc / NCHUNK)       // 32

// ---------------- GEMM geometry ------------------------------------------
// fp16 single-pass GEMM, mbarrier producer/consumer pipeline (no CTA-wide
// __syncthreads in the mainloop). CTA tile 128x128, 256 threads (8 warps),
// warp tile 64M x 32N, 2 CTAs/SM, 3 stages. K tile 64 fp16 (128B rows).
// N rows interleave [Wz 16 | Wh 16] per 32-row j-block.
#define BM 128
#define BN 128
#define NTILES 16                // K = 1024
#define STAGES 3
#define A_BYTES (BM * 128)       // 16384
#define B_BYTES (BN * 128)       // 16384
#define STAGE_BYTES (A_BYTES + B_BYTES)   // 32768
#define SM_BAR (STAGES * STAGE_BYTES)     // 98304
#define SMEM_TOTAL (SM_BAR + 64)          // 98368 per CTA (2 fit/SM)

// ---------------- scratch globals ----------------------------------------
__device__ __align__(1024) __half gx[(size_t)Bc * Tc * Dc];    // fp16 x
__device__ __align__(1024) __half gw[2048 * 1024];             // fp16 [Wz;Wh]
__device__ float2 g_lcv[(size_t)Bc * Tc * Hc];                 // (lc, lv)
__device__ float g_A[NCHUNK * BHc];
__device__ float g_R[NCHUNK * BHc];
__device__ float g_hin[NCHUNK * BHc];

// ---------------- PTX helpers --------------------------------------------
__device__ __forceinline__ uint32_t smem_u32(const void* p) {
    uint32_t a;
    asm("{ .reg .u64 t; cvta.to.shared.u64 t, %1; cvt.u32.u64 %0, t; }"
        : "=r"(a) : "l"(p));
    return a;
}
__device__ __forceinline__ void cp_async16(uint32_t dst, const void* src) {
    asm volatile("cp.async.cg.shared.global [%0], [%1], 16;"
                 :: "r"(dst), "l"(src) : "memory");
}
__device__ __forceinline__ void mbar_init(uint32_t a, uint32_t cnt) {
    asm volatile("mbarrier.init.shared.b64 [%0], %1;" :: "r"(a), "r"(cnt) : "memory");
}
__device__ __forceinline__ void mbar_arrive(uint32_t a) {
    asm volatile("{ .reg .b64 t; mbarrier.arrive.shared.b64 t, [%0]; }"
                 :: "r"(a) : "memory");
}
__device__ __forceinline__ void cp_async_mbar_arrive(uint32_t a) {
    asm volatile("cp.async.mbarrier.arrive.noinc.shared.b64 [%0];"
                 :: "r"(a) : "memory");
}
__device__ __forceinline__ void mbar_wait(uint32_t a, uint32_t parity) {
    asm volatile(
        "{\n\t.reg .pred P;\n"
        "W_%=:\n\t"
        "mbarrier.try_wait.parity.shared.b64 P, [%0], %1;\n\t"
        "@P bra.uni D_%=;\n\t"
        "bra.uni W_%=;\n\t"
        "D_%=:\n\t}" :: "r"(a), "r"(parity) : "memory");
}

#define LDSM_X4(r0, r1, r2, r3, addr) \
    asm volatile("ldmatrix.sync.aligned.m8n8.x4.shared.b16 {%0,%1,%2,%3}, [%4];" \
                 : "=r"(r0), "=r"(r1), "=r"(r2), "=r"(r3) : "r"(addr))

__device__ __forceinline__ void mma_f16(float* c, const uint32_t* a,
                                        const uint32_t* b) {
    asm volatile(
        "mma.sync.aligned.m16n8k16.row.col.f32.f16.f16.f32 "
        "{%0,%1,%2,%3}, {%4,%5,%6,%7}, {%8,%9}, {%0,%1,%2,%3};"
        : "+f"(c[0]), "+f"(c[1]), "+f"(c[2]), "+f"(c[3])
        : "r"(a[0]), "r"(a[1]), "r"(a[2]), "r"(a[3]), "r"(b[0]), "r"(b[1]));
}

// ---------------- math helpers -------------------------------------------
__device__ __forceinline__ float softplus_f(float u) {
    return fmaxf(u, 0.f) + __logf(1.f + __expf(-fabsf(u)));
}
__device__ __forceinline__ float log_g_f(float v) {
    return (v >= 0.f) ? __logf(v + 0.5f) : -softplus_f(-v);
}
__device__ __forceinline__ float logaddexp_f(float a, float b) {
    float m = fmaxf(a, b);
    if (m == -INFINITY) return -INFINITY;
    return m + __logf(1.f + __expf(-fabsf(a - b)));
}
// lc = -softplus(k), lsig = -softplus(-k); share log1p(e^-|k|).
__device__ __forceinline__ void lc_lsig(float k, float& lc, float& lsig) {
    float L = __logf(1.f + __expf(-fabsf(k)));
    lc   = -fmaxf(k, 0.f)  - L;
    lsig = -fmaxf(-k, 0.f) - L;
}

// ===========================================================================
// fp16 convert kernel: x (4,194,304 float4) then [Wz;Wh] (524,288 float4)
// ===========================================================================
__global__ void cvt_kernel(const float4* __restrict__ x,
                           const float4* __restrict__ Wz,
                           const float4* __restrict__ Wh)
{
    int i = blockIdx.x * blockDim.x + threadIdx.x;   // < 4718592
    float4 v;
    uint2* dst;
    if (i < 4194304) {
        v = x[i];
        dst = (uint2*)gx + i;
    } else {
        int j = i - 4194304;                          // 0..524287
        v = (j < 262144) ? Wz[j] : Wh[j - 262144];
        dst = (uint2*)gw + j;
    }
    union { __half h[4]; uint2 u; } o;
    o.h[0] = __float2half_rn(v.x); o.h[1] = __float2half_rn(v.y);
    o.h[2] = __float2half_rn(v.z); o.h[3] = __float2half_rn(v.w);
    *dst = o.u;
}

// ===========================================================================
// fp16 MMA GEMM + fused log-space epilogue, mbarrier pipeline.
// B-tile row r (0..127): j = r>>5 selects the warp-column's 16-wide h block,
// w = r&31: w<16 -> Wz row (n0*64 + j*16 + w), w>=16 -> Wh row (same h).
// ===========================================================================
__device__ __forceinline__ void load_tile(
    int kt, uint32_t sbase, int m0, int n0, int tid)
{
    int kk = kt << 6;                       // fp16 column offset
    uint32_t bB = sbase + A_BYTES;
#pragma unroll
    for (int i = 0; i < 4; i++) {           // A: 128 rows x 8 chunks
        int idx = i * 256 + tid;
        int r = idx >> 3, c = idx & 7;
        uint32_t dst = sbase + r * 128 + ((c ^ (r & 7)) << 4);
        cp_async16(dst, gx + (((size_t)(m0 + r)) << 10) + kk + (c << 3));
    }
#pragma unroll
    for (int i = 0; i < 4; i++) {           // B: 128 rows x 8 chunks
        int idx = i * 256 + tid;
        int r = idx >> 3, c = idx & 7;
        int j = r >> 5, w = r & 31;
        int grow = (w < 16) ? (n0 * 64 + j * 16 + w)
                            : (1024 + n0 * 64 + j * 16 + (w - 16));
        uint32_t dst = bB + r * 128 + ((c ^ (r & 7)) << 4);
        cp_async16(dst, gw + (((size_t)grow) << 10) + kk + (c << 3));
    }
}

__global__ void __launch_bounds__(256, 2) gemm_mma_kernel(
    const float* __restrict__ bz_g, const float* __restrict__ bh_g)
{
    extern __shared__ __align__(1024) char sm[];
    const uint32_t smem_base = smem_u32(sm);
    const int tid = threadIdx.x;
    const int lane = tid & 31;
    const int wid = tid >> 5;
    const int warp_m = wid >> 2;       // 0..1 : 64-row M half
    const int warp_j = wid & 3;        // 0..3 : 32-row N block (16 h)
    const int n0 = blockIdx.x;         // 0..15
    const int m0 = blockIdx.y * BM;

    // barriers: full[s] = SM_BAR + s*8 (count 256, cp.async completions);
    //           empty[s] = SM_BAR + 24 + s*8 (count 8, warp arrivals)
    if (tid == 0) {
#pragma unroll
        for (int s = 0; s < STAGES; s++) {
            mbar_init(smem_base + SM_BAR + s * 8, 256);
            mbar_init(smem_base + SM_BAR + 24 + s * 8, 8);
        }
    }
    __syncthreads();

    float acc[4][4][4];
#pragma unroll
    for (int a = 0; a < 4; a++)
#pragma unroll
        for (int b = 0; b < 4; b++)
#pragma unroll
            for (int c = 0; c < 4; c++) acc[a][b][c] = 0.f;

    load_tile(0, smem_base + 0 * STAGE_BYTES, m0, n0, tid);
    cp_async_mbar_arrive(smem_base + SM_BAR + 0 * 8);
    load_tile(1, smem_base + 1 * STAGE_BYTES, m0, n0, tid);
    cp_async_mbar_arrive(smem_base + SM_BAR + 1 * 8);

    const int a_row = lane & 15;       // m within 16-tile
    const int a_ch  = lane >> 4;       // k half (chunk select)
    const int b_row = lane & 7;        // n within 8-tile
    const int b_kh  = (lane >> 3) & 1; // k half (chunk select)
    const int b_td  = lane >> 4;       // n8 tile within pair

    for (int kt = 0; kt < NTILES; ++kt) {
        // ---- producer: tile kt+2 into stage (kt+2)%3 ----
        int kp = kt + 2;
        if (kp < NTILES) {
            int sp = kp % STAGES;
            int qp = kp / STAGES;
            if (qp >= 1)               // stage reused: wait compute of kp-3
                mbar_wait(smem_base + SM_BAR + 24 + sp * 8,
                          (uint32_t)((qp - 1) & 1));
            load_tile(kp, smem_base + sp * STAGE_BYTES, m0, n0, tid);
            cp_async_mbar_arrive(smem_base + SM_BAR + sp * 8);
        }

        // ---- consumer: tile kt from stage kt%3 ----
        int s = kt % STAGES;
        mbar_wait(smem_base + SM_BAR + s * 8, (uint32_t)((kt / STAGES) & 1));

        const uint32_t aB = smem_base + s * STAGE_BYTES;
        const uint32_t bB = aB + A_BYTES;
#pragma unroll
        for (int ks = 0; ks < 4; ks++) {   // 4 k16 steps per 64-fp16 tile
            uint32_t af[4][4];
#pragma unroll
            for (int mt = 0; mt < 4; mt++) {
                int r = warp_m * 64 + mt * 16 + a_row;
                int ch = (ks * 2 + a_ch) ^ (r & 7);
                LDSM_X4(af[mt][0], af[mt][1], af[mt][2], af[mt][3],
                        aB + r * 128 + ch * 16);
            }
            uint32_t bf[4][2];
#pragma unroll
            for (int tp = 0; tp < 2; tp++) {
                int r = warp_j * 32 + tp * 16 + b_td * 8 + b_row;
                int ch = (ks * 2 + b_kh) ^ (r & 7);
                LDSM_X4(bf[tp * 2][0], bf[tp * 2][1],
                        bf[tp * 2 + 1][0], bf[tp * 2 + 1][1],
                        bB + r * 128 + ch * 16);
            }
#pragma unroll
            for (int mt = 0; mt < 4; mt++)
#pragma unroll
                for (int t = 0; t < 4; t++)
                    mma_f16(acc[mt][t], af[mt], bf[t]);
        }
        __syncwarp();
        if (lane == 0) mbar_arrive(smem_base + SM_BAR + 24 + s * 8);
    }

    // ---------------- fused epilogue (in-register) ------------------------
    // t = 0..1 hold k, t = 2..3 hold h~ for the same h coordinates.
    const int gr = lane >> 2;            // 0..7  (row in m16 tile)
    const int gc = (lane & 3) << 1;      // 0,2,4,6 (col pair)
#pragma unroll
    for (int t = 0; t < 2; t++) {
        int h = n0 * 64 + warp_j * 16 + t * 8 + gc;
        float bz0 = __ldg(bz_g + h),     bz1 = __ldg(bz_g + h + 1);
        float bh0 = __ldg(bh_g + h),     bh1 = __ldg(bh_g + h + 1);
#pragma unroll
        for (int mt = 0; mt < 4; mt++) {
            int r0 = m0 + warp_m * 64 + mt * 16 + gr;
            const float* ck = acc[mt][t];
            const float* ch = acc[mt][t + 2];
#pragma unroll
            for (int rr = 0; rr < 2; rr++) {
                float k0 = ck[rr * 2 + 0] + bz0;
                float k1 = ck[rr * 2 + 1] + bz1;
                float t0 = ch[rr * 2 + 0] + bh0;
                float t1 = ch[rr * 2 + 1] + bh1;
                float4 o;
                float ls0, ls1;
                lc_lsig(k0, o.x, ls0);
                lc_lsig(k1, o.z, ls1);
                o.y = ls0 + log_g_f(t0);
                o.w = ls1 + log_g_f(t1);
                *(float4*)((float*)g_lcv +
                           (((size_t)(r0 + rr * 8)) * Hc + h) * 2) = o;
            }
        }
    }
}

// ===========================================================================
// chunked parallel scan (log-space):  lh <- logaddexp(lh + lc, lv)
// 4 h-adjacent chains per thread, 2 independent float4 loads per step.
// ===========================================================================
__global__ void scan_chunks_kernel()
{
    int g = blockIdx.x * blockDim.x + threadIdx.x;   // < NCHUNK * BHc / 4
    int p = g & (BHc / 4 - 1);
    int c = g >> 10;
    int b = p >> 8;
    int h = (p & 255) << 2;
    size_t base = ((size_t)b * Tc + (size_t)c * CLEN) * Hc + h;
    float A0 = 0.f, R0 = -INFINITY, A1 = 0.f, R1 = -INFINITY;
    float A2 = 0.f, R2 = -INFINITY, A3 = 0.f, R3 = -INFINITY;
#pragma unroll 4
    for (int t = 0; t < CLEN; t++) {
        float4 u = *(const float4*)&g_lcv[base];
        float4 v = *(const float4*)&g_lcv[base + 2];
        base += Hc;
        R0 = logaddexp_f(R0 + u.x, u.y); A0 += u.x;
        R1 = logaddexp_f(R1 + u.z, u.w); A1 += u.z;
        R2 = logaddexp_f(R2 + v.x, v.y); A2 += v.x;
        R3 = logaddexp_f(R3 + v.z, v.w); A3 += v.z;
    }
    int idx = c * BHc + b * Hc + h;
    g_A[idx] = A0; g_A[idx + 1] = A1; g_A[idx + 2] = A2; g_A[idx + 3] = A3;
    g_R[idx] = R0; g_R[idx + 1] = R1; g_R[idx + 2] = R2; g_R[idx + 3] = R3;
}

// warp-parallel combine: 1 warp per chain; lane handles chunks 4L..4L+3;
// compose(P then Q) = (P.A + Q.A, logaddexp(P.R + Q.A, Q.R)).
__global__ void scan_combine_kernel(const float* __restrict__ h0)
{
    int gt = blockIdx.x * blockDim.x + threadIdx.x;
    int w = gt >> 5;                   // chain id < 4096
    int lane = gt & 31;
    float lh0 = log_g_f(__ldg(h0 + w));
    int i0 = (lane * 4) * BHc + w;
    float Al[4], Rl[4];
#pragma unroll
    for (int k = 0; k < 4; k++) {
        Al[k] = g_A[i0 + k * BHc];
        Rl[k] = g_R[i0 + k * BHc];
    }
    float Ai = Al[0], Ri = Rl[0];
#pragma unroll
    for (int k = 1; k < 4; k++) {
        Ri = logaddexp_f(Ri + Al[k], Rl[k]);
        Ai = Ai + Al[k];
    }
#pragma unroll
    for (int d = 1; d < 32; d <<= 1) {
        float Au = __shfl_up_sync(0xFFFFFFFFu, Ai, d);
        float Ru = __shfl_up_sync(0xFFFFFFFFu, Ri, d);
        if (lane >= d) {
            Ri = logaddexp_f(Ru + Ai, Ri);
            Ai = Au + Ai;
        }
    }
    float Ae = __shfl_up_sync(0xFFFFFFFFu, Ai, 1);
    float Re = __shfl_up_sync(0xFFFFFFFFu, Ri, 1);
    if (lane == 0) { Ae = 0.f; Re = -INFINITY; }
#pragma unroll
    for (int k = 0; k < 4; k++) {
        g_hin[i0 + k * BHc] = logaddexp_f(Ae + lh0, Re);
        Re = logaddexp_f(Re + Al[k], Rl[k]);
        Ae = Ae + Al[k];
    }
}

__global__ void scan_final_kernel(float* __restrict__ out)
{
    int g = blockIdx.x * blockDim.x + threadIdx.x;   // < NCHUNK * BHc / 4
    int p = g & (BHc / 4 - 1);
    int c = g >> 10;
    int b = p >> 8;
    int h = (p & 255) << 2;
    size_t base = ((size_t)b * Tc + (size_t)c * CLEN) * Hc + h;
    int idx = c * BHc + b * Hc + h;
    float lh0 = g_hin[idx],     lh1 = g_hin[idx + 1];
    float lh2 = g_hin[idx + 2], lh3 = g_hin[idx + 3];
#pragma unroll 4
    for (int t = 0; t < CLEN; t++) {
        float4 u = *(const float4*)&g_lcv[base];
        float4 v = *(const float4*)&g_lcv[base + 2];
        lh0 = logaddexp_f(lh0 + u.x, u.y);
        lh1 = logaddexp_f(lh1 + u.z, u.w);
        lh2 = logaddexp_f(lh2 + v.x, v.y);
        lh3 = logaddexp_f(lh3 + v.z, v.w);
        float4 o;
        o.x = __expf(lh0); o.y = __expf(lh1);
        o.z = __expf(lh2); o.w = __expf(lh3);
        *(float4*)&out[base] = o;
        base += Hc;
    }
}

// ===========================================================================
extern "C" void kernel_launch(void* const* d_in, const int* in_sizes, int n_in,
                              void* d_out, int out_size)
{
    const float* x  = (const float*)d_in[0];
    const float* h0 = (const float*)d_in[1];
    const float* Wz = (const float*)d_in[2];
    const float* bz = (const float*)d_in[3];
    const float* Wh = (const float*)d_in[4];
    const float* bh = (const float*)d_in[5];
    float* out = (float*)d_out;

    cudaFuncSetAttribute(gemm_mma_kernel,
                         cudaFuncAttributeMaxDynamicSharedMemorySize, SMEM_TOTAL);

    cvt_kernel<<<18432, 256>>>((const float4*)x, (const float4*)Wz,
                               (const float4*)Wh);

    dim3 ggrid(Hc / 64, (Bc * Tc) / BM);   // (16, 128)
    gemm_mma_kernel<<<ggrid, 256, SMEM_TOTAL>>>(bz, bh);

    scan_chunks_kernel<<<(NCHUNK * BHc / 4) / 256, 256>>>();
    scan_combine_kernel<<<(BHc * 32) / 256, 256>>>(h0);
    scan_final_kernel<<<(NCHUNK * BHc / 4) / 256, 256>>>(out);
}

// round 14
// speedup vs baseline: 2.7292x; 1.0585x over previous
#include <cuda_runtime.h>
#include <cuda_fp16.h>
#include <math.h>
#include <stdint.h>

// ---------------- problem dims -------------------------------------------
#define Bc 4
#define Tc 4096
#define Dc 1024
#define Hc 1024
#define BHc (Bc * Hc)
#define NCHUNK 128
#define CLEN (Tc / NCHUNK)       // 32

// ---------------- GEMM geometry ------------------------------------------
// fp16 single-pass GEMM, mbarrier pipeline, fused log-space epilogue AND
// fused per-chunk scan summaries (each CTA owns 4 complete 32-t chunks).
// CTA tile 128x128, 256 threads (8 warps), warp tile 64M x 32N, 2 CTAs/SM.
#define BM 128
#define BN 128
#define NTILES 16                // K = 1024
#define STAGES 3
#define A_BYTES (BM * 128)       // 16384
#define B_BYTES (BN * 128)       // 16384
#define STAGE_BYTES (A_BYTES + B_BYTES)   // 32768
#define SM_BAR (STAGES * STAGE_BYTES)     // 98304
#define SMEM_TOTAL (SM_BAR + 64)          // 98368 per CTA (2 fit/SM)
// epilogue transpose tile aliases the pipeline buffers: [128][67] float2
#define TP_STRIDE 67                      // float2 units; 128*67*8 = 68608 B

// ---------------- scratch globals ----------------------------------------
__device__ __align__(1024) __half gx[(size_t)Bc * Tc * Dc];    // fp16 x
__device__ __align__(1024) __half gw[2048 * 1024];             // fp16 [Wz;Wh]
__device__ float2 g_lcv[(size_t)Bc * Tc * Hc];                 // (lc, lv)
__device__ float g_A[NCHUNK * BHc];
__device__ float g_R[NCHUNK * BHc];
__device__ float g_hin[NCHUNK * BHc];

// ---------------- PTX helpers --------------------------------------------
__device__ __forceinline__ uint32_t smem_u32(const void* p) {
    uint32_t a;
    asm("{ .reg .u64 t; cvta.to.shared.u64 t, %1; cvt.u32.u64 %0, t; }"
        : "=r"(a) : "l"(p));
    return a;
}
__device__ __forceinline__ void cp_async16(uint32_t dst, const void* src) {
    asm volatile("cp.async.cg.shared.global [%0], [%1], 16;"
                 :: "r"(dst), "l"(src) : "memory");
}
__device__ __forceinline__ void mbar_init(uint32_t a, uint32_t cnt) {
    asm volatile("mbarrier.init.shared.b64 [%0], %1;" :: "r"(a), "r"(cnt) : "memory");
}
__device__ __forceinline__ void mbar_arrive(uint32_t a) {
    asm volatile("{ .reg .b64 t; mbarrier.arrive.shared.b64 t, [%0]; }"
                 :: "r"(a) : "memory");
}
__device__ __forceinline__ void cp_async_mbar_arrive(uint32_t a) {
    asm volatile("cp.async.mbarrier.arrive.noinc.shared.b64 [%0];"
                 :: "r"(a) : "memory");
}
__device__ __forceinline__ void mbar_wait(uint32_t a, uint32_t parity) {
    asm volatile(
        "{\n\t.reg .pred P;\n"
        "W_%=:\n\t"
        "mbarrier.try_wait.parity.shared.b64 P, [%0], %1;\n\t"
        "@P bra.uni D_%=;\n\t"
        "bra.uni W_%=;\n\t"
        "D_%=:\n\t}" :: "r"(a), "r"(parity) : "memory");
}

#define LDSM_X4(r0, r1, r2, r3, addr) \
    asm volatile("ldmatrix.sync.aligned.m8n8.x4.shared.b16 {%0,%1,%2,%3}, [%4];" \
                 : "=r"(r0), "=r"(r1), "=r"(r2), "=r"(r3) : "r"(addr))

__device__ __forceinline__ void mma_f16(float* c, const uint32_t* a,
                                        const uint32_t* b) {
    asm volatile(
        "mma.sync.aligned.m16n8k16.row.col.f32.f16.f16.f32 "
        "{%0,%1,%2,%3}, {%4,%5,%6,%7}, {%8,%9}, {%0,%1,%2,%3};"
        : "+f"(c[0]), "+f"(c[1]), "+f"(c[2]), "+f"(c[3])
        : "r"(a[0]), "r"(a[1]), "r"(a[2]), "r"(a[3]), "r"(b[0]), "r"(b[1]));
}

// ---------------- math helpers -------------------------------------------
__device__ __forceinline__ float softplus_f(float u) {
    return fmaxf(u, 0.f) + __logf(1.f + __expf(-fabsf(u)));
}
__device__ __forceinline__ float log_g_f(float v) {
    return (v >= 0.f) ? __logf(v + 0.5f) : -softplus_f(-v);
}
__device__ __forceinline__ float logaddexp_f(float a, float b) {
    float m = fmaxf(a, b);
    if (m == -INFINITY) return -INFINITY;
    return m + __logf(1.f + __expf(-fabsf(a - b)));
}
// lc = -softplus(k), lsig = -softplus(-k); share log1p(e^-|k|).
__device__ __forceinline__ void lc_lsig(float k, float& lc, float& lsig) {
    float L = __logf(1.f + __expf(-fabsf(k)));
    lc   = -fmaxf(k, 0.f)  - L;
    lsig = -fmaxf(-k, 0.f) - L;
}

// ===========================================================================
// fp16 convert kernel: x (4,194,304 float4) then [Wz;Wh] (524,288 float4)
// ===========================================================================
__global__ void cvt_kernel(const float4* __restrict__ x,
                           const float4* __restrict__ Wz,
                           const float4* __restrict__ Wh)
{
    int i = blockIdx.x * blockDim.x + threadIdx.x;   // < 4718592
    float4 v;
    uint2* dst;
    if (i < 4194304) {
        v = x[i];
        dst = (uint2*)gx + i;
    } else {
        int j = i - 4194304;                          // 0..524287
        v = (j < 262144) ? Wz[j] : Wh[j - 262144];
        dst = (uint2*)gw + j;
    }
    union { __half h[4]; uint2 u; } o;
    o.h[0] = __float2half_rn(v.x); o.h[1] = __float2half_rn(v.y);
    o.h[2] = __float2half_rn(v.z); o.h[3] = __float2half_rn(v.w);
    *dst = o.u;
}

// ===========================================================================
// fp16 MMA GEMM + fused epilogue (g_lcv + chunk summaries g_A/g_R).
// B-tile row r (0..127): j = r>>5 selects the warp-column's 16-wide h block,
// w = r&31: w<16 -> Wz row (n0*64 + j*16 + w), w>=16 -> Wh row (same h).
// ===========================================================================
__device__ __forceinline__ void load_tile(
    int kt, uint32_t sbase, int m0, int n0, int tid)
{
    int kk = kt << 6;                       // fp16 column offset
    uint32_t bB = sbase + A_BYTES;
#pragma unroll
    for (int i = 0; i < 4; i++) {           // A: 128 rows x 8 chunks
        int idx = i * 256 + tid;
        int r = idx >> 3, c = idx & 7;
        uint32_t dst = sbase + r * 128 + ((c ^ (r & 7)) << 4);
        cp_async16(dst, gx + (((size_t)(m0 + r)) << 10) + kk + (c << 3));
    }
#pragma unroll
    for (int i = 0; i < 4; i++) {           // B: 128 rows x 8 chunks
        int idx = i * 256 + tid;
        int r = idx >> 3, c = idx & 7;
        int j = r >> 5, w = r & 31;
        int grow = (w < 16) ? (n0 * 64 + j * 16 + w)
                            : (1024 + n0 * 64 + j * 16 + (w - 16));
        uint32_t dst = bB + r * 128 + ((c ^ (r & 7)) << 4);
        cp_async16(dst, gw + (((size_t)grow) << 10) + kk + (c << 3));
    }
}

__global__ void __launch_bounds__(256, 2) gemm_mma_kernel(
    const float* __restrict__ bz_g, const float* __restrict__ bh_g)
{
    extern __shared__ __align__(1024) char sm[];
    const uint32_t smem_base = smem_u32(sm);
    const int tid = threadIdx.x;
    const int lane = tid & 31;
    const int wid = tid >> 5;
    const int warp_m = wid >> 2;       // 0..1 : 64-row M half
    const int warp_j = wid & 3;        // 0..3 : 32-row N block (16 h)
    const int n0 = blockIdx.x;         // 0..15
    const int m0 = blockIdx.y * BM;

    // barriers: full[s] = SM_BAR + s*8 (count 256, cp.async completions);
    //           empty[s] = SM_BAR + 24 + s*8 (count 8, warp arrivals)
    if (tid == 0) {
#pragma unroll
        for (int s = 0; s < STAGES; s++) {
            mbar_init(smem_base + SM_BAR + s * 8, 256);
            mbar_init(smem_base + SM_BAR + 24 + s * 8, 8);
        }
    }
    __syncthreads();

    float acc[4][4][4];
#pragma unroll
    for (int a = 0; a < 4; a++)
#pragma unroll
        for (int b = 0; b < 4; b++)
#pragma unroll
            for (int c = 0; c < 4; c++) acc[a][b][c] = 0.f;

    load_tile(0, smem_base + 0 * STAGE_BYTES, m0, n0, tid);
    cp_async_mbar_arrive(smem_base + SM_BAR + 0 * 8);
    load_tile(1, smem_base + 1 * STAGE_BYTES, m0, n0, tid);
    cp_async_mbar_arrive(smem_base + SM_BAR + 1 * 8);

    const int a_row = lane & 15;       // m within 16-tile
    const int a_ch  = lane >> 4;       // k half (chunk select)
    const int b_row = lane & 7;        // n within 8-tile
    const int b_kh  = (lane >> 3) & 1; // k half (chunk select)
    const int b_td  = lane >> 4;       // n8 tile within pair

    for (int kt = 0; kt < NTILES; ++kt) {
        // ---- producer: tile kt+2 into stage (kt+2)%3 ----
        int kp = kt + 2;
        if (kp < NTILES) {
            int sp = kp % STAGES;
            int qp = kp / STAGES;
            if (qp >= 1)               // stage reused: wait compute of kp-3
                mbar_wait(smem_base + SM_BAR + 24 + sp * 8,
                          (uint32_t)((qp - 1) & 1));
            load_tile(kp, smem_base + sp * STAGE_BYTES, m0, n0, tid);
            cp_async_mbar_arrive(smem_base + SM_BAR + sp * 8);
        }

        // ---- consumer: tile kt from stage kt%3 ----
        int s = kt % STAGES;
        mbar_wait(smem_base + SM_BAR + s * 8, (uint32_t)((kt / STAGES) & 1));

        const uint32_t aB = smem_base + s * STAGE_BYTES;
        const uint32_t bB = aB + A_BYTES;
#pragma unroll
        for (int ks = 0; ks < 4; ks++) {   // 4 k16 steps per 64-fp16 tile
            uint32_t af[4][4];
#pragma unroll
            for (int mt = 0; mt < 4; mt++) {
                int r = warp_m * 64 + mt * 16 + a_row;
                int ch = (ks * 2 + a_ch) ^ (r & 7);
                LDSM_X4(af[mt][0], af[mt][1], af[mt][2], af[mt][3],
                        aB + r * 128 + ch * 16);
            }
            uint32_t bf[4][2];
#pragma unroll
            for (int tp = 0; tp < 2; tp++) {
                int r = warp_j * 32 + tp * 16 + b_td * 8 + b_row;
                int ch = (ks * 2 + b_kh) ^ (r & 7);
                LDSM_X4(bf[tp * 2][0], bf[tp * 2][1],
                        bf[tp * 2 + 1][0], bf[tp * 2 + 1][1],
                        bB + r * 128 + ch * 16);
            }
#pragma unroll
            for (int mt = 0; mt < 4; mt++)
#pragma unroll
                for (int t = 0; t < 4; t++)
                    mma_f16(acc[mt][t], af[mt], bf[t]);
        }
        __syncwarp();
        if (lane == 0) mbar_arrive(smem_base + SM_BAR + 24 + s * 8);
    }

    // ---------------- fused epilogue (in-register) ------------------------
    // t = 0..1 hold k, t = 2..3 hold h~ for the same h coordinates.
    // Writes g_lcv AND stores (lc,lv) into the smem transpose tile for the
    // fused chunk-summary pass (pipeline smem is dead now; sync first).
    __syncthreads();                       // all stages consumed; alias smem
    float2* tp = (float2*)sm;              // [128][TP_STRIDE]

    const int gr = lane >> 2;            // 0..7  (row in m16 tile)
    const int gc = (lane & 3) << 1;      // 0,2,4,6 (col pair)
#pragma unroll
    for (int t = 0; t < 2; t++) {
        int hloc = warp_j * 16 + t * 8 + gc;     // local h 0..63
        int h = n0 * 64 + hloc;
        float bz0 = __ldg(bz_g + h),     bz1 = __ldg(bz_g + h + 1);
        float bh0 = __ldg(bh_g + h),     bh1 = __ldg(bh_g + h + 1);
#pragma unroll
        for (int mt = 0; mt < 4; mt++) {
            int rloc = warp_m * 64 + mt * 16 + gr;   // local t row
            int r0 = m0 + rloc;
            const float* ck = acc[mt][t];
            const float* ch = acc[mt][t + 2];
#pragma unroll
            for (int rr = 0; rr < 2; rr++) {
                float k0 = ck[rr * 2 + 0] + bz0;
                float k1 = ck[rr * 2 + 1] + bz1;
                float t0 = ch[rr * 2 + 0] + bh0;
                float t1 = ch[rr * 2 + 1] + bh1;
                float4 o;
                float ls0, ls1;
                lc_lsig(k0, o.x, ls0);
                lc_lsig(k1, o.z, ls1);
                o.y = ls0 + log_g_f(t0);
                o.w = ls1 + log_g_f(t1);
                *(float4*)((float*)g_lcv +
                           (((size_t)(r0 + rr * 8)) * Hc + h) * 2) = o;
                float2* row = tp + (rloc + rr * 8) * TP_STRIDE + hloc;
                row[0] = make_float2(o.x, o.y);
                row[1] = make_float2(o.z, o.w);
            }
        }
    }

    // ---------------- fused chunk summaries -------------------------------
    // 4 chunks x 64 h = 256 threads; each scans 32 sequential t in smem.
    __syncthreads();
    {
        int c  = tid >> 6;                 // 0..3 local chunk
        int hl = tid & 63;                 // local h
        const float2* p = tp + (c * CLEN) * TP_STRIDE + hl;
        float A = 0.f, R = -INFINITY;
#pragma unroll 4
        for (int t = 0; t < CLEN; t++) {
            float2 v = *p; p += TP_STRIDE;
            R = logaddexp_f(R + v.x, v.y);
            A += v.x;
        }
        int bb = m0 >> 12;                               // batch
        int cg = ((m0 & (Tc - 1)) >> 5) + c;             // global chunk
        int idx = cg * BHc + bb * Hc + n0 * 64 + hl;
        g_A[idx] = A;
        g_R[idx] = R;
    }
}

// ===========================================================================
// warp-parallel combine: 1 warp per chain; lane handles chunks 4L..4L+3;
// compose(P then Q) = (P.A + Q.A, logaddexp(P.R + Q.A, Q.R)).
// ===========================================================================
__global__ void scan_combine_kernel(const float* __restrict__ h0)
{
    int gt = blockIdx.x * blockDim.x + threadIdx.x;
    int w = gt >> 5;                   // chain id < 4096
    int lane = gt & 31;
    float lh0 = log_g_f(__ldg(h0 + w));
    int i0 = (lane * 4) * BHc + w;
    float Al[4], Rl[4];
#pragma unroll
    for (int k = 0; k < 4; k++) {
        Al[k] = g_A[i0 + k * BHc];
        Rl[k] = g_R[i0 + k * BHc];
    }
    float Ai = Al[0], Ri = Rl[0];
#pragma unroll
    for (int k = 1; k < 4; k++) {
        Ri = logaddexp_f(Ri + Al[k], Rl[k]);
        Ai = Ai + Al[k];
    }
#pragma unroll
    for (int d = 1; d < 32; d <<= 1) {
        float Au = __shfl_up_sync(0xFFFFFFFFu, Ai, d);
        float Ru = __shfl_up_sync(0xFFFFFFFFu, Ri, d);
        if (lane >= d) {
            Ri = logaddexp_f(Ru + Ai, Ri);
            Ai = Au + Ai;
        }
    }
    float Ae = __shfl_up_sync(0xFFFFFFFFu, Ai, 1);
    float Re = __shfl_up_sync(0xFFFFFFFFu, Ri, 1);
    if (lane == 0) { Ae = 0.f; Re = -INFINITY; }
#pragma unroll
    for (int k = 0; k < 4; k++) {
        g_hin[i0 + k * BHc] = logaddexp_f(Ae + lh0, Re);
        Re = logaddexp_f(Re + Al[k], Rl[k]);
        Ae = Ae + Al[k];
    }
}

// ===========================================================================
// final pass: lh <- logaddexp(lh + lc, lv); out = exp(lh)
// 4 h-adjacent chains per thread, 2 independent float4 loads per step.
// ===========================================================================
__global__ void scan_final_kernel(float* __restrict__ out)
{
    int g = blockIdx.x * blockDim.x + threadIdx.x;   // < NCHUNK * BHc / 4
    int p = g & (BHc / 4 - 1);
    int c = g >> 10;
    int b = p >> 8;
    int h = (p & 255) << 2;
    size_t base = ((size_t)b * Tc + (size_t)c * CLEN) * Hc + h;
    int idx = c * BHc + b * Hc + h;
    float lh0 = g_hin[idx],     lh1 = g_hin[idx + 1];
    float lh2 = g_hin[idx + 2], lh3 = g_hin[idx + 3];
#pragma unroll 4
    for (int t = 0; t < CLEN; t++) {
        float4 u = *(const float4*)&g_lcv[base];
        float4 v = *(const float4*)&g_lcv[base + 2];
        lh0 = logaddexp_f(lh0 + u.x, u.y);
        lh1 = logaddexp_f(lh1 + u.z, u.w);
        lh2 = logaddexp_f(lh2 + v.x, v.y);
        lh3 = logaddexp_f(lh3 + v.z, v.w);
        float4 o;
        o.x = __expf(lh0); o.y = __expf(lh1);
        o.z = __expf(lh2); o.w = __expf(lh3);
        *(float4*)&out[base] = o;
        base += Hc;
    }
}

// ===========================================================================
extern "C" void kernel_launch(void* const* d_in, const int* in_sizes, int n_in,
                              void* d_out, int out_size)
{
    const float* x  = (const float*)d_in[0];
    const float* h0 = (const float*)d_in[1];
    const float* Wz = (const float*)d_in[2];
    const float* bz = (const float*)d_in[3];
    const float* Wh = (const float*)d_in[4];
    const float* bh = (const float*)d_in[5];
    float* out = (float*)d_out;

    cudaFuncSetAttribute(gemm_mma_kernel,
                         cudaFuncAttributeMaxDynamicSharedMemorySize, SMEM_TOTAL);

    cvt_kernel<<<18432, 256>>>((const float4*)x, (const float4*)Wz,
                               (const float4*)Wh);

    dim3 ggrid(Hc / 64, (Bc * Tc) / BM);   // (16, 128)
    gemm_mma_kernel<<<ggrid, 256, SMEM_TOTAL>>>(bz, bh);

    scan_combine_kernel<<<(BHc * 32) / 256, 256>>>(h0);
    scan_final_kernel<<<(NCHUNK * BHc / 4) / 256, 256>>>(out);
}